// round 7
// baseline (speedup 1.0000x reference)
#include <cuda_runtime.h>
#include <math.h>

#define NN 50000
#define NE 600000
#define DD 128
#define NL 4
#define NG 512
#define NT 10
#define EPSF 1e-5f

// ---------------- scratch (static device allocations) ----------------
__device__ int   g_deg[NN];
__device__ int   g_rowptr[NN + 1];
__device__ int   g_cursor[NN];
__device__ int   g_srcperm[NE];
__device__ float g_amp[NN], g_att[NN], g_dinv[NN];
__device__ float g_delta_acc;
__device__ float g_h[NN * DD];
__device__ unsigned g_aggsT[(size_t)NN * 4 * DD];   // [N][512] tf32 bits: mean|min|max|std
__device__ float g_out[NN * DD];
__device__ float g_bnsum[DD], g_bnsq[DD];
__device__ float g_mu[DD], g_rsg[DD], g_bt[DD];
__device__ int   g_gcnt[NG];
__device__ int   g_goff[NG + 1];
__device__ float g_pool[NG * DD];
__device__ unsigned g_Wt[(size_t)NL * 384 * 512];   // tf32 bits: [l][n'=slab*128+n][k'=k%512]

// ---------------- small helpers ----------------
__device__ __forceinline__ float4 f4zero() { return make_float4(0.f, 0.f, 0.f, 0.f); }

__device__ __forceinline__ unsigned f2tf(float f) {
    unsigned u;
    asm("cvt.rna.tf32.f32 %0, %1;" : "=r"(u) : "f"(f));
    return u;
}

__device__ __forceinline__ void cp_async16(unsigned smem_addr, const void* gptr) {
    asm volatile("cp.async.cg.shared.global [%0], [%1], 16;" :: "r"(smem_addr), "l"(gptr));
}
__device__ __forceinline__ void cp_async16p(unsigned smem_addr, const void* gptr, int szbytes) {
    asm volatile("cp.async.cg.shared.global [%0], [%1], 16, %2;"
                 :: "r"(smem_addr), "l"(gptr), "r"(szbytes));
}
__device__ __forceinline__ void cp_commit() { asm volatile("cp.async.commit_group;"); }
__device__ __forceinline__ void cp_wait0() { asm volatile("cp.async.wait_group 0;"); }

// ---------------- setup kernels ----------------
__global__ void k_zero() {
    int i = blockIdx.x * blockDim.x + threadIdx.x;
    if (i < NN) { g_deg[i] = 0; g_cursor[i] = 0; }
    if (i < NG) g_gcnt[i] = 0;
    if (i == 0) g_delta_acc = 0.f;
}

__global__ void k_hist(const int* __restrict__ ei, const int* __restrict__ batch) {
    int e = blockIdx.x * blockDim.x + threadIdx.x;
    if (e < NE) atomicAdd(&g_deg[ei[NE + e]], 1);     // dst row
    if (e < NN) atomicAdd(&g_gcnt[batch[e]], 1);
}

__global__ void k_scan() {
    __shared__ int s[1024];
    int t = threadIdx.x;
    const int C = (NN + 1023) / 1024;
    int base = t * C;
    int acc = 0;
    for (int c = 0; c < C; c++) { int i = base + c; if (i < NN) acc += g_deg[i]; }
    s[t] = acc;
    __syncthreads();
    for (int d = 1; d < 1024; d <<= 1) {
        int add = (t >= d) ? s[t - d] : 0;
        __syncthreads();
        s[t] += add;
        __syncthreads();
    }
    int off = s[t] - acc;
    for (int c = 0; c < C; c++) { int i = base + c; if (i < NN) { g_rowptr[i] = off; off += g_deg[i]; } }
    if (t == 0) g_rowptr[NN] = NE;
    __syncthreads();
    int v = (t < NG) ? g_gcnt[t] : 0;
    s[t] = v;
    __syncthreads();
    for (int d = 1; d < 1024; d <<= 1) {
        int add = (t >= d) ? s[t - d] : 0;
        __syncthreads();
        s[t] += add;
        __syncthreads();
    }
    if (t < NG) g_goff[t] = s[t] - v;
    if (t == 0) g_goff[NG] = NN;
}

__global__ void k_delta() {
    int i = blockIdx.x * blockDim.x + threadIdx.x;
    float v = (i < NN) ? log1pf((float)g_deg[i]) : 0.f;
    for (int o = 16; o; o >>= 1) v += __shfl_down_sync(0xffffffffu, v, o);
    __shared__ float ws[8];
    if ((threadIdx.x & 31) == 0) ws[threadIdx.x >> 5] = v;
    __syncthreads();
    if (threadIdx.x < 8) {
        v = ws[threadIdx.x];
        for (int o = 4; o; o >>= 1) v += __shfl_down_sync(0xffu, v, o);
        if (threadIdx.x == 0) atomicAdd(&g_delta_acc, v);
    }
}

__global__ void k_scalars() {
    int i = blockIdx.x * blockDim.x + threadIdx.x;
    if (i >= NN) return;
    float deg = (float)g_deg[i];
    float d = fmaxf(deg, 1.f);
    float ld = log1pf(d);
    float delta = g_delta_acc / (float)NN;
    g_amp[i] = ld / delta;
    g_att[i] = delta / ld;
    g_dinv[i] = 1.f / d;
}

__global__ void k_scatter(const int* __restrict__ ei) {
    int e = blockIdx.x * blockDim.x + threadIdx.x;
    if (e >= NE) return;
    int dst = ei[NE + e];
    int p = atomicAdd(&g_cursor[dst], 1);
    g_srcperm[g_rowptr[dst] + p] = ei[e];
}

__global__ void k_emb(const float* __restrict__ x, const float* __restrict__ W,
                      const float* __restrict__ b) {
    int t = blockIdx.x * blockDim.x + threadIdx.x;
    int i = t >> 5, c = t & 31;
    if (i >= NN) return;
    float x0 = x[i * 3 + 0], x1 = x[i * 3 + 1], x2 = x[i * 3 + 2];
    float4 w0 = *(const float4*)&W[0 * DD + c * 4];
    float4 w1 = *(const float4*)&W[1 * DD + c * 4];
    float4 w2 = *(const float4*)&W[2 * DD + c * 4];
    float4 bb = *(const float4*)&b[c * 4];
    float4 h;
    h.x = bb.x + x0 * w0.x + x1 * w1.x + x2 * w2.x;
    h.y = bb.y + x0 * w0.y + x1 * w1.y + x2 * w2.y;
    h.z = bb.z + x0 * w0.z + x1 * w1.z + x2 * w2.z;
    h.w = bb.w + x0 * w0.w + x1 * w1.w + x2 * w2.w;
    ((float4*)g_h)[i * 32 + c] = h;
}

// tf32-convert + relayout conv weights: g_Wt[l][slab*128+n][k%512] = cvt(W[l][k][n])
__global__ void k_wprep(const float* __restrict__ conv_W) {
    int t = blockIdx.x * blockDim.x + threadIdx.x;
    if (t >= NL * 1536 * DD) return;
    int l = t / (1536 * DD);
    int r = t - l * (1536 * DD);
    int k = r >> 7;           // 0..1535
    int n = r & 127;          // coalesced read along n
    int slab = k >> 9;
    int kp = k & 511;
    g_Wt[((size_t)l * 384 + slab * 128 + n) * 512 + kp] = f2tf(conv_W[t]);
}

// ---------------- per-layer kernels ----------------
__global__ void k_agg() {
    if (blockIdx.x == 0 && threadIdx.x < DD) {    // reset BN accumulators for this layer
        g_bnsum[threadIdx.x] = 0.f;
        g_bnsq[threadIdx.x] = 0.f;
    }
    int warp = (blockIdx.x * blockDim.x + threadIdx.x) >> 5;
    int lane = threadIdx.x & 31;
    if (warp >= NN) return;
    int beg = g_rowptr[warp], end = g_rowptr[warp + 1];
    float4 s1 = f4zero(), s2 = f4zero();
    float4 mn = make_float4(INFINITY, INFINITY, INFINITY, INFINITY);
    float4 mx = make_float4(-INFINITY, -INFINITY, -INFINITY, -INFINITY);
    const float4* hp = (const float4*)g_h;
    for (int e = beg; e < end; e += 32) {
        int myj = (e + lane < end) ? g_srcperm[e + lane] : 0;
        int cnt = min(32, end - e);
#pragma unroll 4
        for (int kk = 0; kk < cnt; kk++) {
            int j = __shfl_sync(0xffffffffu, myj, kk);
            float4 m = hp[j * 32 + lane];
            s1.x += m.x; s1.y += m.y; s1.z += m.z; s1.w += m.w;
            s2.x += m.x * m.x; s2.y += m.y * m.y; s2.z += m.z * m.z; s2.w += m.w * m.w;
            mn.x = fminf(mn.x, m.x); mn.y = fminf(mn.y, m.y); mn.z = fminf(mn.z, m.z); mn.w = fminf(mn.w, m.w);
            mx.x = fmaxf(mx.x, m.x); mx.y = fmaxf(mx.y, m.y); mx.z = fmaxf(mx.z, m.z); mx.w = fmaxf(mx.w, m.w);
        }
    }
    float dinv = g_dinv[warp];
    float4 mean, sd;
    mean.x = s1.x * dinv; mean.y = s1.y * dinv; mean.z = s1.z * dinv; mean.w = s1.w * dinv;
    sd.x = sqrtf(fmaxf(s2.x * dinv - mean.x * mean.x, 0.f) + EPSF);
    sd.y = sqrtf(fmaxf(s2.y * dinv - mean.y * mean.y, 0.f) + EPSF);
    sd.z = sqrtf(fmaxf(s2.z * dinv - mean.z * mean.z, 0.f) + EPSF);
    sd.w = sqrtf(fmaxf(s2.w * dinv - mean.w * mean.w, 0.f) + EPSF);
    if (beg == end) { mn = f4zero(); mx = f4zero(); }
    // write tf32 bits directly (A matrix for the GEMM)
    uint4* A = (uint4*)(g_aggsT + (size_t)warp * 4 * DD);
    A[0 * 32 + lane] = make_uint4(f2tf(mean.x), f2tf(mean.y), f2tf(mean.z), f2tf(mean.w));
    A[1 * 32 + lane] = make_uint4(f2tf(mn.x), f2tf(mn.y), f2tf(mn.z), f2tf(mn.w));
    A[2 * 32 + lane] = make_uint4(f2tf(mx.x), f2tf(mx.y), f2tf(mx.z), f2tf(mx.w));
    A[3 * 32 + lane] = make_uint4(f2tf(sd.x), f2tf(sd.y), f2tf(sd.z), f2tf(sd.w));
}

// ---------------- TF32 tensor-core GEMM with in-register slab folding ----------------
// out = P0 + amp*P1 + att*P2 + bias,  P_s = aggs @ W_s (K=512 each, 3 n-tiles in sequence).
// BN stats fused into epilogue.
#define BM 128
#define BK 16
#define SST 20              // 16 + 4 pad
#define NCC 96              // 3 ntiles * 32 chunks

__global__ __launch_bounds__(256) void k_gemm(const unsigned* __restrict__ Wt2,
                                              const float* __restrict__ bl) {
    __shared__ unsigned sA[2][BM * SST];
    __shared__ unsigned sB[2][DD * SST];
    __shared__ float sAmp[BM], sAtt[BM], sBias[DD];
    __shared__ float sSum[DD], sSq[DD];

    int bm = blockIdx.x * BM;
    int tid = threadIdx.x;
    int lane = tid & 31;
    int warp = tid >> 5;
    int g = lane >> 2;
    int t = lane & 3;
    int m_base = (warp >> 2) * 64;
    int n_base = (warp & 3) * 32;

    if (tid < BM) {
        int r = bm + tid;
        sAmp[tid] = (r < NN) ? g_amp[r] : 0.f;
        sAtt[tid] = (r < NN) ? g_att[r] : 0.f;
        sBias[tid] = bl[tid];
        sSum[tid] = 0.f;
        sSq[tid] = 0.f;
    }
    __syncthreads();

    float acc[4][4][4], accH[4][4][4];
#pragma unroll
    for (int i = 0; i < 4; i++)
#pragma unroll
        for (int j = 0; j < 4; j++)
#pragma unroll
            for (int c = 0; c < 4; c++) { acc[i][j][c] = 0.f; accH[i][j][c] = 0.f; }

    auto cpAB = [&](int cc, int buf) {
        int koff = (cc & 31) * BK;
        int nrow0 = (cc >> 5) * 128;
#pragma unroll
        for (int u = 0; u < 2; u++) {
            int s = tid + u * 256;      // 0..511
            int row = s >> 2;           // 0..127
            int k4 = (s & 3) * 4;       // word offset 0,4,8,12
            unsigned da = (unsigned)__cvta_generic_to_shared(&sA[buf][row * SST + k4]);
            const unsigned* pa = g_aggsT + (size_t)(bm + row) * 512 + koff + k4;
            cp_async16p(da, pa, (bm + row < NN) ? 16 : 0);
            unsigned db = (unsigned)__cvta_generic_to_shared(&sB[buf][row * SST + k4]);
            cp_async16(db, Wt2 + (size_t)(nrow0 + row) * 512 + koff + k4);
        }
    };
    auto mmaChunk = [&](int buf) {
#pragma unroll
        for (int ks = 0; ks < BK; ks += 8) {
            unsigned bfrag[4][2];
#pragma unroll
            for (int j = 0; j < 4; j++) {
                int n = n_base + j * 8 + g;
                bfrag[j][0] = sB[buf][n * SST + ks + t];
                bfrag[j][1] = sB[buf][n * SST + ks + t + 4];
            }
#pragma unroll
            for (int i = 0; i < 4; i++) {
                int m0 = m_base + i * 16 + g;
                unsigned a0 = sA[buf][m0 * SST + ks + t];
                unsigned a1 = sA[buf][(m0 + 8) * SST + ks + t];
                unsigned a2 = sA[buf][m0 * SST + ks + t + 4];
                unsigned a3 = sA[buf][(m0 + 8) * SST + ks + t + 4];
#pragma unroll
                for (int j = 0; j < 4; j++) {
                    asm volatile(
                        "mma.sync.aligned.m16n8k8.row.col.f32.tf32.tf32.f32 "
                        "{%0,%1,%2,%3}, {%4,%5,%6,%7}, {%8,%9}, {%0,%1,%2,%3};"
                        : "+f"(acc[i][j][0]), "+f"(acc[i][j][1]),
                          "+f"(acc[i][j][2]), "+f"(acc[i][j][3])
                        : "r"(a0), "r"(a1), "r"(a2), "r"(a3),
                          "r"(bfrag[j][0]), "r"(bfrag[j][1]));
                }
            }
        }
    };

    cpAB(0, 0);
    cp_commit();

    for (int cc = 0; cc < NCC; cc++) {
        int cur = cc & 1;
        cp_wait0();
        __syncthreads();
        if (cc + 1 < NCC) {
            cpAB(cc + 1, cur ^ 1);
            cp_commit();
        }
        mmaChunk(cur);
        if (cc == 31) {           // accH = P0
#pragma unroll
            for (int i = 0; i < 4; i++)
#pragma unroll
                for (int j = 0; j < 4; j++)
#pragma unroll
                    for (int c = 0; c < 4; c++) { accH[i][j][c] = acc[i][j][c]; acc[i][j][c] = 0.f; }
        } else if (cc == 63) {    // accH += amp * P1
#pragma unroll
            for (int i = 0; i < 4; i++) {
                float a0 = sAmp[m_base + i * 16 + g];
                float a1 = sAmp[m_base + i * 16 + g + 8];
#pragma unroll
                for (int j = 0; j < 4; j++) {
                    accH[i][j][0] += a0 * acc[i][j][0]; accH[i][j][1] += a0 * acc[i][j][1];
                    accH[i][j][2] += a1 * acc[i][j][2]; accH[i][j][3] += a1 * acc[i][j][3];
                    acc[i][j][0] = 0.f; acc[i][j][1] = 0.f; acc[i][j][2] = 0.f; acc[i][j][3] = 0.f;
                }
            }
        }
    }
    // accH += att * P2, then bias
#pragma unroll
    for (int i = 0; i < 4; i++) {
        float a0 = sAtt[m_base + i * 16 + g];
        float a1 = sAtt[m_base + i * 16 + g + 8];
#pragma unroll
        for (int j = 0; j < 4; j++) {
            int col = n_base + j * 8 + t * 2;
            float b0 = sBias[col], b1 = sBias[col + 1];
            accH[i][j][0] = accH[i][j][0] + a0 * acc[i][j][0] + b0;
            accH[i][j][1] = accH[i][j][1] + a0 * acc[i][j][1] + b1;
            accH[i][j][2] = accH[i][j][2] + a1 * acc[i][j][2] + b0;
            accH[i][j][3] = accH[i][j][3] + a1 * acc[i][j][3] + b1;
        }
    }

    // store out tile
#pragma unroll
    for (int i = 0; i < 4; i++) {
        int r0 = bm + m_base + i * 16 + g;
        int r1 = r0 + 8;
#pragma unroll
        for (int j = 0; j < 4; j++) {
            int col = n_base + j * 8 + t * 2;
            if (r0 < NN)
                *(float2*)&g_out[(size_t)r0 * DD + col] = make_float2(accH[i][j][0], accH[i][j][1]);
            if (r1 < NN)
                *(float2*)&g_out[(size_t)r1 * DD + col] = make_float2(accH[i][j][2], accH[i][j][3]);
        }
    }

    // fused BN stats: per-column sum/sumsq over valid rows
#pragma unroll
    for (int j = 0; j < 4; j++)
#pragma unroll
        for (int c2 = 0; c2 < 2; c2++) {
            int col = n_base + j * 8 + t * 2 + c2;
            float s = 0.f, q = 0.f;
#pragma unroll
            for (int i = 0; i < 4; i++) {
                int r0 = bm + m_base + i * 16 + g;
                float v0 = accH[i][j][c2];
                float v1 = accH[i][j][2 + c2];
                if (r0 < NN) { s += v0; q += v0 * v0; }
                if (r0 + 8 < NN) { s += v1; q += v1 * v1; }
            }
            // reduce over g (lane bits 2..4)
#pragma unroll
            for (int m = 4; m <= 16; m <<= 1) {
                s += __shfl_xor_sync(0xffffffffu, s, m);
                q += __shfl_xor_sync(0xffffffffu, q, m);
            }
            if (g == 0) {
                atomicAdd(&sSum[col], s);
                atomicAdd(&sSq[col], q);
            }
        }
    __syncthreads();
    if (tid < DD) {
        atomicAdd(&g_bnsum[tid], sSum[tid]);
        atomicAdd(&g_bnsq[tid], sSq[tid]);
    }
}

__global__ void k_bnfin(const float* __restrict__ gamma, const float* __restrict__ beta) {
    int f = threadIdx.x;
    float mu = g_bnsum[f] / (float)NN;
    float var = g_bnsq[f] / (float)NN - mu * mu;
    float rs = rsqrtf(var + EPSF);
    g_mu[f] = mu;
    g_rsg[f] = rs * gamma[f];
    g_bt[f] = beta[f];
}

__global__ void k_bnapply() {
    int t = blockIdx.x * blockDim.x + threadIdx.x;
    if (t >= NN * 32) return;
    int c = (t & 31) * 4;
    float4 o = ((const float4*)g_out)[t];
    float4 h = ((float4*)g_h)[t];
    o.x = fmaxf((o.x - g_mu[c + 0]) * g_rsg[c + 0] + g_bt[c + 0], 0.f) + h.x;
    o.y = fmaxf((o.y - g_mu[c + 1]) * g_rsg[c + 1] + g_bt[c + 1], 0.f) + h.y;
    o.z = fmaxf((o.z - g_mu[c + 2]) * g_rsg[c + 2] + g_bt[c + 2], 0.f) + h.z;
    o.w = fmaxf((o.w - g_mu[c + 3]) * g_rsg[c + 3] + g_bt[c + 3], 0.f) + h.w;
    ((float4*)g_h)[t] = o;
}

// ---------------- pooling + MLP ----------------
__global__ void k_pool() {
    int warp = (blockIdx.x * blockDim.x + threadIdx.x) >> 5;
    int lane = threadIdx.x & 31;
    if (warp >= NG) return;
    int beg = g_goff[warp], end = g_goff[warp + 1];
    float4 s = f4zero();
    const float4* hp = (const float4*)g_h;
    for (int r = beg; r < end; r++) {
        float4 v = hp[r * 32 + lane];
        s.x += v.x; s.y += v.y; s.z += v.z; s.w += v.w;
    }
    float inv = 1.f / (float)max(end - beg, 1);
    s.x *= inv; s.y *= inv; s.z *= inv; s.w *= inv;
    ((float4*)g_pool)[warp * 32 + lane] = s;
}

__global__ void k_mlp(const float* __restrict__ W1, const float* __restrict__ b1,
                      const float* __restrict__ W2, const float* __restrict__ b2,
                      const float* __restrict__ W3, const float* __restrict__ b3,
                      float* __restrict__ out) {
    __shared__ float sg[DD], sz1[64], sz2[32];
    int gid = blockIdx.x;
    int tid = threadIdx.x;      // 128
    sg[tid] = g_pool[gid * DD + tid];
    __syncthreads();
    if (tid < 64) {
        float a = b1[tid];
        for (int k = 0; k < DD; k++) a += sg[k] * W1[k * 64 + tid];
        sz1[tid] = fmaxf(a, 0.f);
    }
    __syncthreads();
    if (tid < 32) {
        float a = b2[tid];
        for (int k = 0; k < 64; k++) a += sz1[k] * W2[k * 32 + tid];
        sz2[tid] = fmaxf(a, 0.f);
    }
    __syncthreads();
    if (tid < NT) {
        float a = b3[tid];
        for (int k = 0; k < 32; k++) a += sz2[k] * W3[k * NT + tid];
        out[gid * NT + tid] = a;
    }
}

// ---------------- launch ----------------
extern "C" void kernel_launch(void* const* d_in, const int* in_sizes, int n_in,
                              void* d_out, int out_size) {
    const float* x      = (const float*)d_in[0];
    const int*   ei     = (const int*)d_in[1];
    const int*   batch  = (const int*)d_in[2];
    const float* emb_W  = (const float*)d_in[3];
    const float* emb_b  = (const float*)d_in[4];
    const float* conv_W = (const float*)d_in[5];
    const float* conv_b = (const float*)d_in[6];
    const float* bng    = (const float*)d_in[7];
    const float* bnb    = (const float*)d_in[8];
    const float* W1     = (const float*)d_in[9];
    const float* b1     = (const float*)d_in[10];
    const float* W2     = (const float*)d_in[11];
    const float* b2     = (const float*)d_in[12];
    const float* W3     = (const float*)d_in[13];
    const float* b3     = (const float*)d_in[14];
    float* out = (float*)d_out;

    k_zero<<<(NN + 255) / 256, 256>>>();
    k_hist<<<(NE + 255) / 256, 256>>>(ei, batch);
    k_scan<<<1, 1024>>>();
    k_delta<<<(NN + 255) / 256, 256>>>();
    k_scalars<<<(NN + 255) / 256, 256>>>();
    k_scatter<<<(NE + 255) / 256, 256>>>(ei);
    k_emb<<<(NN * 32 + 255) / 256, 256>>>(x, emb_W, emb_b);
    k_wprep<<<(NL * 1536 * DD + 255) / 256, 256>>>(conv_W);

    unsigned* g_Wt_ptr;
    cudaGetSymbolAddress((void**)&g_Wt_ptr, g_Wt);

    for (int l = 0; l < NL; l++) {
        k_agg<<<(NN * 32 + 255) / 256, 256>>>();
        k_gemm<<<(NN + BM - 1) / BM, 256>>>(g_Wt_ptr + (size_t)l * 384 * 512,
                                            conv_b + (size_t)l * DD);
        k_bnfin<<<1, DD>>>(bng + (size_t)l * DD, bnb + (size_t)l * DD);
        k_bnapply<<<(NN * 32 + 255) / 256, 256>>>();
    }

    k_pool<<<(NG * 32 + 255) / 256, 256>>>();
    k_mlp<<<NG, DD>>>(W1, b1, W2, b2, W3, b3, out);
}

// round 8
// speedup vs baseline: 1.4509x; 1.4509x over previous
#include <cuda_runtime.h>
#include <cuda_fp16.h>
#include <math.h>

#define NN 50000
#define NE 600000
#define DD 128
#define NL 4
#define NG 512
#define NT 10
#define EPSF 1e-5f

// ---------------- scratch (static device allocations) ----------------
__device__ int   g_deg[NN];
__device__ int   g_rowptr[NN + 1];
__device__ int   g_cursor[NN];
__device__ int   g_srcperm[NE];
__device__ float g_amp[NN], g_att[NN], g_dinv[NN];
__device__ float g_delta_acc;
__device__ float g_h[NN * DD];
__device__ float g_aggs[(size_t)NN * 4 * DD];   // [N][512] fp32: mean|min|max|std
__device__ float g_out[NN * DD];
__device__ float g_bnsum[DD], g_bnsq[DD];
__device__ float g_mu[DD], g_rsg[DD], g_bt[DD];
__device__ int   g_gcnt[NG];
__device__ int   g_goff[NG + 1];
__device__ float g_pool[NG * DD];
__device__ __half g_WtH[(size_t)NL * DD * 1536];   // W transposed fp16: [l][n][k]

// ---------------- small helpers ----------------
__device__ __forceinline__ float4 f4zero() { return make_float4(0.f, 0.f, 0.f, 0.f); }

__device__ __forceinline__ unsigned packh2(float a, float b) {
    __half2 h = __floats2half2_rn(a, b);
    return *(unsigned*)&h;
}

__device__ __forceinline__ void cp_async16(unsigned smem_addr, const void* gptr) {
    asm volatile("cp.async.cg.shared.global [%0], [%1], 16;" :: "r"(smem_addr), "l"(gptr));
}
__device__ __forceinline__ void cp_commit() { asm volatile("cp.async.commit_group;"); }
__device__ __forceinline__ void cp_wait0() { asm volatile("cp.async.wait_group 0;"); }

// ---------------- setup kernels ----------------
__global__ void k_zero() {
    int i = blockIdx.x * blockDim.x + threadIdx.x;
    if (i < NN) { g_deg[i] = 0; g_cursor[i] = 0; }
    if (i < NG) g_gcnt[i] = 0;
    if (i == 0) g_delta_acc = 0.f;
}

__global__ void k_hist(const int* __restrict__ ei, const int* __restrict__ batch) {
    int e = blockIdx.x * blockDim.x + threadIdx.x;
    if (e < NE) atomicAdd(&g_deg[ei[NE + e]], 1);     // dst row
    if (e < NN) atomicAdd(&g_gcnt[batch[e]], 1);
}

__global__ void k_scan() {
    __shared__ int s[1024];
    int t = threadIdx.x;
    const int C = (NN + 1023) / 1024;
    int base = t * C;
    int acc = 0;
    for (int c = 0; c < C; c++) { int i = base + c; if (i < NN) acc += g_deg[i]; }
    s[t] = acc;
    __syncthreads();
    for (int d = 1; d < 1024; d <<= 1) {
        int add = (t >= d) ? s[t - d] : 0;
        __syncthreads();
        s[t] += add;
        __syncthreads();
    }
    int off = s[t] - acc;
    for (int c = 0; c < C; c++) { int i = base + c; if (i < NN) { g_rowptr[i] = off; off += g_deg[i]; } }
    if (t == 0) g_rowptr[NN] = NE;
    __syncthreads();
    int v = (t < NG) ? g_gcnt[t] : 0;
    s[t] = v;
    __syncthreads();
    for (int d = 1; d < 1024; d <<= 1) {
        int add = (t >= d) ? s[t - d] : 0;
        __syncthreads();
        s[t] += add;
        __syncthreads();
    }
    if (t < NG) g_goff[t] = s[t] - v;
    if (t == 0) g_goff[NG] = NN;
}

__global__ void k_delta() {
    int i = blockIdx.x * blockDim.x + threadIdx.x;
    float v = (i < NN) ? log1pf((float)g_deg[i]) : 0.f;
    for (int o = 16; o; o >>= 1) v += __shfl_down_sync(0xffffffffu, v, o);
    __shared__ float ws[8];
    if ((threadIdx.x & 31) == 0) ws[threadIdx.x >> 5] = v;
    __syncthreads();
    if (threadIdx.x < 8) {
        v = ws[threadIdx.x];
        for (int o = 4; o; o >>= 1) v += __shfl_down_sync(0xffu, v, o);
        if (threadIdx.x == 0) atomicAdd(&g_delta_acc, v);
    }
}

__global__ void k_scalars() {
    int i = blockIdx.x * blockDim.x + threadIdx.x;
    if (i >= NN) return;
    float deg = (float)g_deg[i];
    float d = fmaxf(deg, 1.f);
    float ld = log1pf(d);
    float delta = g_delta_acc / (float)NN;
    g_amp[i] = ld / delta;
    g_att[i] = delta / ld;
    g_dinv[i] = 1.f / d;
}

__global__ void k_scatter(const int* __restrict__ ei) {
    int e = blockIdx.x * blockDim.x + threadIdx.x;
    if (e >= NE) return;
    int dst = ei[NE + e];
    int p = atomicAdd(&g_cursor[dst], 1);
    g_srcperm[g_rowptr[dst] + p] = ei[e];
}

__global__ void k_emb(const float* __restrict__ x, const float* __restrict__ W,
                      const float* __restrict__ b) {
    int t = blockIdx.x * blockDim.x + threadIdx.x;
    int i = t >> 5, c = t & 31;
    if (i >= NN) return;
    float x0 = x[i * 3 + 0], x1 = x[i * 3 + 1], x2 = x[i * 3 + 2];
    float4 w0 = *(const float4*)&W[0 * DD + c * 4];
    float4 w1 = *(const float4*)&W[1 * DD + c * 4];
    float4 w2 = *(const float4*)&W[2 * DD + c * 4];
    float4 bb = *(const float4*)&b[c * 4];
    float4 h;
    h.x = bb.x + x0 * w0.x + x1 * w1.x + x2 * w2.x;
    h.y = bb.y + x0 * w0.y + x1 * w1.y + x2 * w2.y;
    h.z = bb.z + x0 * w0.z + x1 * w1.z + x2 * w2.z;
    h.w = bb.w + x0 * w0.w + x1 * w1.w + x2 * w2.w;
    ((float4*)g_h)[i * 32 + c] = h;
}

// Transpose + fp16-convert conv weights: g_WtH[l][n][k] = half(W[l][k][n])
__global__ void k_wprep(const float* __restrict__ conv_W) {
    int t = blockIdx.x * blockDim.x + threadIdx.x;
    if (t >= NL * 1536 * DD) return;
    int l = t / (1536 * DD);
    int r = t - l * (1536 * DD);
    int k = r >> 7;           // 0..1535
    int n = r & 127;          // coalesced read along n
    g_WtH[((size_t)l * DD + n) * 1536 + k] = __float2half_rn(conv_W[t]);
}

// ---------------- per-layer kernels ----------------
__global__ void k_agg() {
    if (blockIdx.x == 0 && threadIdx.x < DD) {    // reset BN accumulators for this layer
        g_bnsum[threadIdx.x] = 0.f;
        g_bnsq[threadIdx.x] = 0.f;
    }
    int warp = (blockIdx.x * blockDim.x + threadIdx.x) >> 5;
    int lane = threadIdx.x & 31;
    if (warp >= NN) return;
    int beg = g_rowptr[warp], end = g_rowptr[warp + 1];
    float4 s1 = f4zero(), s2 = f4zero();
    float4 mn = make_float4(INFINITY, INFINITY, INFINITY, INFINITY);
    float4 mx = make_float4(-INFINITY, -INFINITY, -INFINITY, -INFINITY);
    const float4* hp = (const float4*)g_h;
    for (int e = beg; e < end; e += 32) {
        int myj = (e + lane < end) ? g_srcperm[e + lane] : 0;
        int cnt = min(32, end - e);
#pragma unroll 4
        for (int kk = 0; kk < cnt; kk++) {
            int j = __shfl_sync(0xffffffffu, myj, kk);
            float4 m = hp[j * 32 + lane];
            s1.x += m.x; s1.y += m.y; s1.z += m.z; s1.w += m.w;
            s2.x += m.x * m.x; s2.y += m.y * m.y; s2.z += m.z * m.z; s2.w += m.w * m.w;
            mn.x = fminf(mn.x, m.x); mn.y = fminf(mn.y, m.y); mn.z = fminf(mn.z, m.z); mn.w = fminf(mn.w, m.w);
            mx.x = fmaxf(mx.x, m.x); mx.y = fmaxf(mx.y, m.y); mx.z = fmaxf(mx.z, m.z); mx.w = fmaxf(mx.w, m.w);
        }
    }
    float dinv = g_dinv[warp];
    float4 mean, sd;
    mean.x = s1.x * dinv; mean.y = s1.y * dinv; mean.z = s1.z * dinv; mean.w = s1.w * dinv;
    sd.x = sqrtf(fmaxf(s2.x * dinv - mean.x * mean.x, 0.f) + EPSF);
    sd.y = sqrtf(fmaxf(s2.y * dinv - mean.y * mean.y, 0.f) + EPSF);
    sd.z = sqrtf(fmaxf(s2.z * dinv - mean.z * mean.z, 0.f) + EPSF);
    sd.w = sqrtf(fmaxf(s2.w * dinv - mean.w * mean.w, 0.f) + EPSF);
    if (beg == end) { mn = f4zero(); mx = f4zero(); }
    float4* A = (float4*)(g_aggs + (size_t)warp * 4 * DD);
    A[0 * 32 + lane] = mean;
    A[1 * 32 + lane] = mn;
    A[2 * 32 + lane] = mx;
    A[3 * 32 + lane] = sd;
}

// ---------------- FP16 tensor-core GEMM (m16n8k16), double-buffered ----------------
// C[128 x 128] per block; 8 warps each 64x32. BK=16 halves = 1 k-step per chunk.
#define BM 128
#define BK 16
#define SSTH 12             // words per row (8 used + 4 pad): conflict-free fragments
#define NCHUNK 96           // 1536 / BK

__global__ __launch_bounds__(256, 2) void k_gemm(const __half* __restrict__ WtH,
                                                 const float* __restrict__ bl) {
    __shared__ unsigned sA[2][BM * SSTH];
    __shared__ unsigned sB[2][DD * SSTH];
    __shared__ float sAmp[BM], sAtt[BM], sBias[DD];
    __shared__ float sSum[DD], sSq[DD];

    int bm = blockIdx.x * BM;
    int tid = threadIdx.x;
    int lane = tid & 31;
    int warp = tid >> 5;
    int g = lane >> 2;
    int t = lane & 3;
    int m_base = (warp >> 2) * 64;
    int n_base = (warp & 3) * 32;

    if (tid < BM) {
        int r = bm + tid;
        sAmp[tid] = (r < NN) ? g_amp[r] : 0.f;
        sAtt[tid] = (r < NN) ? g_att[r] : 0.f;
        sBias[tid] = bl[tid];
        sSum[tid] = 0.f;
        sSq[tid] = 0.f;
    }
    __syncthreads();

    float acc[4][4][4];
#pragma unroll
    for (int i = 0; i < 4; i++)
#pragma unroll
        for (int j = 0; j < 4; j++)
#pragma unroll
            for (int c = 0; c < 4; c++) acc[i][j][c] = 0.f;

    // A/B staging: thread covers row = tid>>1, segment seg = tid&1 (8 halves each)
    const int row = tid >> 1;
    const int seg = tid & 1;
    const bool rowOK = (bm + row) < NN;

    float4 aR0, aR1;

    auto loadA = [&](int chunk) {
        int koff = (chunk * BK) & 511;
        if (rowOK) {
            const float* p = g_aggs + (size_t)(bm + row) * 512 + koff + seg * 8;
            aR0 = *(const float4*)p;
            aR1 = *(const float4*)(p + 4);
        } else { aR0 = f4zero(); aR1 = f4zero(); }
    };
    auto storeA = [&](int chunk, int buf) {
        int slab = (chunk * BK) >> 9;
        float sc = (slab == 0) ? 1.f : ((slab == 1) ? sAmp[row] : sAtt[row]);
        uint4 v;
        v.x = packh2(aR0.x * sc, aR0.y * sc);
        v.y = packh2(aR0.z * sc, aR0.w * sc);
        v.z = packh2(aR1.x * sc, aR1.y * sc);
        v.w = packh2(aR1.z * sc, aR1.w * sc);
        *(uint4*)&sA[buf][row * SSTH + seg * 4] = v;
    };
    auto cpB = [&](int chunk, int buf) {
        unsigned dst = (unsigned)__cvta_generic_to_shared(&sB[buf][row * SSTH + seg * 4]);
        cp_async16(dst, WtH + (size_t)row * 1536 + chunk * BK + seg * 8);
    };
    auto mmaChunk = [&](int buf) {
        unsigned bfrag[4][2];
#pragma unroll
        for (int j = 0; j < 4; j++) {
            int n = n_base + j * 8 + g;
            bfrag[j][0] = sB[buf][n * SSTH + t];
            bfrag[j][1] = sB[buf][n * SSTH + t + 4];
        }
#pragma unroll
        for (int i = 0; i < 4; i++) {
            int m0 = m_base + i * 16 + g;
            unsigned a0 = sA[buf][m0 * SSTH + t];
            unsigned a1 = sA[buf][(m0 + 8) * SSTH + t];
            unsigned a2 = sA[buf][m0 * SSTH + t + 4];
            unsigned a3 = sA[buf][(m0 + 8) * SSTH + t + 4];
#pragma unroll
            for (int j = 0; j < 4; j++) {
                asm volatile(
                    "mma.sync.aligned.m16n8k16.row.col.f32.f16.f16.f32 "
                    "{%0,%1,%2,%3}, {%4,%5,%6,%7}, {%8,%9}, {%0,%1,%2,%3};"
                    : "+f"(acc[i][j][0]), "+f"(acc[i][j][1]),
                      "+f"(acc[i][j][2]), "+f"(acc[i][j][3])
                    : "r"(a0), "r"(a1), "r"(a2), "r"(a3),
                      "r"(bfrag[j][0]), "r"(bfrag[j][1]));
            }
        }
    };

    // prologue
    loadA(0);
    cpB(0, 0);
    cp_commit();
    storeA(0, 0);
    cp_wait0();
    __syncthreads();

    for (int c = 0; c < NCHUNK; c++) {
        int cur = c & 1;
        if (c + 1 < NCHUNK) {
            loadA(c + 1);
            cpB(c + 1, cur ^ 1);
            cp_commit();
        }
        mmaChunk(cur);
        if (c + 1 < NCHUNK) storeA(c + 1, cur ^ 1);
        cp_wait0();
        __syncthreads();
    }

    // epilogue: bias + store
#pragma unroll
    for (int i = 0; i < 4; i++) {
        int r0 = bm + m_base + i * 16 + g;
        int r1 = r0 + 8;
#pragma unroll
        for (int j = 0; j < 4; j++) {
            int col = n_base + j * 8 + t * 2;
            float bx = sBias[col], by = sBias[col + 1];
            acc[i][j][0] += bx; acc[i][j][1] += by;
            acc[i][j][2] += bx; acc[i][j][3] += by;
            if (r0 < NN)
                *(float2*)&g_out[(size_t)r0 * DD + col] = make_float2(acc[i][j][0], acc[i][j][1]);
            if (r1 < NN)
                *(float2*)&g_out[(size_t)r1 * DD + col] = make_float2(acc[i][j][2], acc[i][j][3]);
        }
    }

    // fused BN stats: per-column sum/sumsq over valid rows
#pragma unroll
    for (int j = 0; j < 4; j++)
#pragma unroll
        for (int c2 = 0; c2 < 2; c2++) {
            int col = n_base + j * 8 + t * 2 + c2;
            float s = 0.f, q = 0.f;
#pragma unroll
            for (int i = 0; i < 4; i++) {
                int r0 = bm + m_base + i * 16 + g;
                float v0 = acc[i][j][c2];
                float v1 = acc[i][j][2 + c2];
                if (r0 < NN) { s += v0; q += v0 * v0; }
                if (r0 + 8 < NN) { s += v1; q += v1 * v1; }
            }
#pragma unroll
            for (int m = 4; m <= 16; m <<= 1) {
                s += __shfl_xor_sync(0xffffffffu, s, m);
                q += __shfl_xor_sync(0xffffffffu, q, m);
            }
            if (g == 0) {
                atomicAdd(&sSum[col], s);
                atomicAdd(&sSq[col], q);
            }
        }
    __syncthreads();
    if (tid < DD) {
        atomicAdd(&g_bnsum[tid], sSum[tid]);
        atomicAdd(&g_bnsq[tid], sSq[tid]);
    }
}

__global__ void k_bnfin(const float* __restrict__ gamma, const float* __restrict__ beta) {
    int f = threadIdx.x;
    float mu = g_bnsum[f] / (float)NN;
    float var = g_bnsq[f] / (float)NN - mu * mu;
    float rs = rsqrtf(var + EPSF);
    g_mu[f] = mu;
    g_rsg[f] = rs * gamma[f];
    g_bt[f] = beta[f];
}

__global__ void k_bnapply() {
    int t = blockIdx.x * blockDim.x + threadIdx.x;
    if (t >= NN * 32) return;
    int c = (t & 31) * 4;
    float4 o = ((const float4*)g_out)[t];
    float4 h = ((float4*)g_h)[t];
    o.x = fmaxf((o.x - g_mu[c + 0]) * g_rsg[c + 0] + g_bt[c + 0], 0.f) + h.x;
    o.y = fmaxf((o.y - g_mu[c + 1]) * g_rsg[c + 1] + g_bt[c + 1], 0.f) + h.y;
    o.z = fmaxf((o.z - g_mu[c + 2]) * g_rsg[c + 2] + g_bt[c + 2], 0.f) + h.z;
    o.w = fmaxf((o.w - g_mu[c + 3]) * g_rsg[c + 3] + g_bt[c + 3], 0.f) + h.w;
    ((float4*)g_h)[t] = o;
}

// ---------------- pooling + MLP ----------------
__global__ void k_pool() {
    int warp = (blockIdx.x * blockDim.x + threadIdx.x) >> 5;
    int lane = threadIdx.x & 31;
    if (warp >= NG) return;
    int beg = g_goff[warp], end = g_goff[warp + 1];
    float4 s = f4zero();
    const float4* hp = (const float4*)g_h;
    for (int r = beg; r < end; r++) {
        float4 v = hp[r * 32 + lane];
        s.x += v.x; s.y += v.y; s.z += v.z; s.w += v.w;
    }
    float inv = 1.f / (float)max(end - beg, 1);
    s.x *= inv; s.y *= inv; s.z *= inv; s.w *= inv;
    ((float4*)g_pool)[warp * 32 + lane] = s;
}

__global__ void k_mlp(const float* __restrict__ W1, const float* __restrict__ b1,
                      const float* __restrict__ W2, const float* __restrict__ b2,
                      const float* __restrict__ W3, const float* __restrict__ b3,
                      float* __restrict__ out) {
    __shared__ float sg[DD], sz1[64], sz2[32];
    int gid = blockIdx.x;
    int tid = threadIdx.x;      // 128
    sg[tid] = g_pool[gid * DD + tid];
    __syncthreads();
    if (tid < 64) {
        float a = b1[tid];
        for (int k = 0; k < DD; k++) a += sg[k] * W1[k * 64 + tid];
        sz1[tid] = fmaxf(a, 0.f);
    }
    __syncthreads();
    if (tid < 32) {
        float a = b2[tid];
        for (int k = 0; k < 64; k++) a += sz1[k] * W2[k * 32 + tid];
        sz2[tid] = fmaxf(a, 0.f);
    }
    __syncthreads();
    if (tid < NT) {
        float a = b3[tid];
        for (int k = 0; k < 32; k++) a += sz2[k] * W3[k * NT + tid];
        out[gid * NT + tid] = a;
    }
}

// ---------------- launch ----------------
extern "C" void kernel_launch(void* const* d_in, const int* in_sizes, int n_in,
                              void* d_out, int out_size) {
    const float* x      = (const float*)d_in[0];
    const int*   ei     = (const int*)d_in[1];
    const int*   batch  = (const int*)d_in[2];
    const float* emb_W  = (const float*)d_in[3];
    const float* emb_b  = (const float*)d_in[4];
    const float* conv_W = (const float*)d_in[5];
    const float* conv_b = (const float*)d_in[6];
    const float* bng    = (const float*)d_in[7];
    const float* bnb    = (const float*)d_in[8];
    const float* W1     = (const float*)d_in[9];
    const float* b1     = (const float*)d_in[10];
    const float* W2     = (const float*)d_in[11];
    const float* b2     = (const float*)d_in[12];
    const float* W3     = (const float*)d_in[13];
    const float* b3     = (const float*)d_in[14];
    float* out = (float*)d_out;

    k_zero<<<(NN + 255) / 256, 256>>>();
    k_hist<<<(NE + 255) / 256, 256>>>(ei, batch);
    k_scan<<<1, 1024>>>();
    k_delta<<<(NN + 255) / 256, 256>>>();
    k_scalars<<<(NN + 255) / 256, 256>>>();
    k_scatter<<<(NE + 255) / 256, 256>>>(ei);
    k_emb<<<(NN * 32 + 255) / 256, 256>>>(x, emb_W, emb_b);
    k_wprep<<<(NL * 1536 * DD + 255) / 256, 256>>>(conv_W);

    __half* g_WtH_ptr;
    cudaGetSymbolAddress((void**)&g_WtH_ptr, g_WtH);

    for (int l = 0; l < NL; l++) {
        k_agg<<<(NN * 32 + 255) / 256, 256>>>();
        k_gemm<<<(NN + BM - 1) / BM, 256>>>(g_WtH_ptr + (size_t)l * DD * 1536,
                                            conv_b + (size_t)l * DD);
        k_bnfin<<<1, DD>>>(bng + (size_t)l * DD, bnb + (size_t)l * DD);
        k_bnapply<<<(NN * 32 + 255) / 256, 256>>>();
    }

    k_pool<<<(NG * 32 + 255) / 256, 256>>>();
    k_mlp<<<NG, DD>>>(W1, b1, W2, b2, W3, b3, out);
}

// round 9
// speedup vs baseline: 1.6639x; 1.1468x over previous
#include <cuda_runtime.h>
#include <cuda_fp16.h>
#include <math.h>

#define NN 50000
#define NE 600000
#define DD 128
#define NL 4
#define NG 512
#define NT 10
#define EPSF 1e-5f

// ---------------- scratch (static device allocations) ----------------
__device__ int   g_deg[NN];
__device__ int   g_rowptr[NN + 1];
__device__ int   g_cursor[NN];
__device__ int   g_srcperm[NE];
__device__ float g_amp[NN], g_att[NN], g_dinv[NN];
__device__ float g_delta_acc;
__device__ float g_h[NN * DD];
__device__ unsigned g_hH[NN * DD / 2];              // fp16 mirror of g_h (packed half2)
__device__ unsigned g_aggsH[(size_t)NN * 768];      // [N][1536] halves: [aggs|amp*aggs|att*aggs]
__device__ float g_out[NN * DD];
__device__ float g_bnsum[DD], g_bnsq[DD];
__device__ float g_mu[DD], g_rsg[DD], g_bt[DD];
__device__ int   g_gcnt[NG];
__device__ int   g_goff[NG + 1];
__device__ float g_pool[NG * DD];
__device__ __half g_WtH[(size_t)NL * DD * 1536];    // W transposed fp16: [l][n][k]

// ---------------- small helpers ----------------
__device__ __forceinline__ float4 f4zero() { return make_float4(0.f, 0.f, 0.f, 0.f); }

__device__ __forceinline__ unsigned packh2(float a, float b) {
    __half2 h = __floats2half2_rn(a, b);
    return *(unsigned*)&h;
}

__device__ __forceinline__ void cp_async16(unsigned smem_addr, const void* gptr) {
    asm volatile("cp.async.cg.shared.global [%0], [%1], 16;" :: "r"(smem_addr), "l"(gptr));
}
__device__ __forceinline__ void cp_async16p(unsigned smem_addr, const void* gptr, int szbytes) {
    asm volatile("cp.async.cg.shared.global [%0], [%1], 16, %2;"
                 :: "r"(smem_addr), "l"(gptr), "r"(szbytes));
}
__device__ __forceinline__ void cp_commit() { asm volatile("cp.async.commit_group;"); }
__device__ __forceinline__ void cp_wait1() { asm volatile("cp.async.wait_group 1;"); }

// ---------------- setup kernels ----------------
__global__ void k_zero() {
    int i = blockIdx.x * blockDim.x + threadIdx.x;
    if (i < NN) { g_deg[i] = 0; g_cursor[i] = 0; }
    if (i < NG) g_gcnt[i] = 0;
    if (i == 0) g_delta_acc = 0.f;
}

__global__ void k_hist(const int* __restrict__ ei, const int* __restrict__ batch) {
    int e = blockIdx.x * blockDim.x + threadIdx.x;
    if (e < NE) atomicAdd(&g_deg[ei[NE + e]], 1);     // dst row
    if (e < NN) atomicAdd(&g_gcnt[batch[e]], 1);
}

__global__ void k_scan() {
    __shared__ int s[1024];
    int t = threadIdx.x;
    const int C = (NN + 1023) / 1024;
    int base = t * C;
    int acc = 0;
    for (int c = 0; c < C; c++) { int i = base + c; if (i < NN) acc += g_deg[i]; }
    s[t] = acc;
    __syncthreads();
    for (int d = 1; d < 1024; d <<= 1) {
        int add = (t >= d) ? s[t - d] : 0;
        __syncthreads();
        s[t] += add;
        __syncthreads();
    }
    int off = s[t] - acc;
    for (int c = 0; c < C; c++) { int i = base + c; if (i < NN) { g_rowptr[i] = off; off += g_deg[i]; } }
    if (t == 0) g_rowptr[NN] = NE;
    __syncthreads();
    int v = (t < NG) ? g_gcnt[t] : 0;
    s[t] = v;
    __syncthreads();
    for (int d = 1; d < 1024; d <<= 1) {
        int add = (t >= d) ? s[t - d] : 0;
        __syncthreads();
        s[t] += add;
        __syncthreads();
    }
    if (t < NG) g_goff[t] = s[t] - v;
    if (t == 0) g_goff[NG] = NN;
}

__global__ void k_delta() {
    int i = blockIdx.x * blockDim.x + threadIdx.x;
    float v = (i < NN) ? log1pf((float)g_deg[i]) : 0.f;
    for (int o = 16; o; o >>= 1) v += __shfl_down_sync(0xffffffffu, v, o);
    __shared__ float ws[8];
    if ((threadIdx.x & 31) == 0) ws[threadIdx.x >> 5] = v;
    __syncthreads();
    if (threadIdx.x < 8) {
        v = ws[threadIdx.x];
        for (int o = 4; o; o >>= 1) v += __shfl_down_sync(0xffu, v, o);
        if (threadIdx.x == 0) atomicAdd(&g_delta_acc, v);
    }
}

__global__ void k_scalars() {
    int i = blockIdx.x * blockDim.x + threadIdx.x;
    if (i >= NN) return;
    float deg = (float)g_deg[i];
    float d = fmaxf(deg, 1.f);
    float ld = log1pf(d);
    float delta = g_delta_acc / (float)NN;
    g_amp[i] = ld / delta;
    g_att[i] = delta / ld;
    g_dinv[i] = 1.f / d;
}

__global__ void k_scatter(const int* __restrict__ ei) {
    int e = blockIdx.x * blockDim.x + threadIdx.x;
    if (e >= NE) return;
    int dst = ei[NE + e];
    int p = atomicAdd(&g_cursor[dst], 1);
    g_srcperm[g_rowptr[dst] + p] = ei[e];
}

__global__ void k_emb(const float* __restrict__ x, const float* __restrict__ W,
                      const float* __restrict__ b) {
    int t = blockIdx.x * blockDim.x + threadIdx.x;
    int i = t >> 5, c = t & 31;
    if (i >= NN) return;
    float x0 = x[i * 3 + 0], x1 = x[i * 3 + 1], x2 = x[i * 3 + 2];
    float4 w0 = *(const float4*)&W[0 * DD + c * 4];
    float4 w1 = *(const float4*)&W[1 * DD + c * 4];
    float4 w2 = *(const float4*)&W[2 * DD + c * 4];
    float4 bb = *(const float4*)&b[c * 4];
    float4 h;
    h.x = bb.x + x0 * w0.x + x1 * w1.x + x2 * w2.x;
    h.y = bb.y + x0 * w0.y + x1 * w1.y + x2 * w2.y;
    h.z = bb.z + x0 * w0.z + x1 * w1.z + x2 * w2.z;
    h.w = bb.w + x0 * w0.w + x1 * w1.w + x2 * w2.w;
    ((float4*)g_h)[i * 32 + c] = h;
    ((uint2*)g_hH)[i * 32 + c] = make_uint2(packh2(h.x, h.y), packh2(h.z, h.w));
}

// Transpose + fp16-convert conv weights: g_WtH[l][n][k] = half(W[l][k][n])
__global__ void k_wprep(const float* __restrict__ conv_W) {
    int t = blockIdx.x * blockDim.x + threadIdx.x;
    if (t >= NL * 1536 * DD) return;
    int l = t / (1536 * DD);
    int r = t - l * (1536 * DD);
    int k = r >> 7;           // 0..1535
    int n = r & 127;          // coalesced read along n
    g_WtH[((size_t)l * DD + n) * 1536 + k] = __float2half_rn(conv_W[t]);
}

// ---------------- per-layer kernels ----------------
// warp per node; gathers fp16 h rows; writes pre-scaled fp16 A matrix (3 slabs).
__global__ void k_agg() {
    if (blockIdx.x == 0 && threadIdx.x < DD) {    // reset BN accumulators for this layer
        g_bnsum[threadIdx.x] = 0.f;
        g_bnsq[threadIdx.x] = 0.f;
    }
    int warp = (blockIdx.x * blockDim.x + threadIdx.x) >> 5;
    int lane = threadIdx.x & 31;
    if (warp >= NN) return;
    int beg = g_rowptr[warp], end = g_rowptr[warp + 1];
    float4 s1 = f4zero(), s2 = f4zero();
    float4 mn = make_float4(INFINITY, INFINITY, INFINITY, INFINITY);
    float4 mx = make_float4(-INFINITY, -INFINITY, -INFINITY, -INFINITY);
    const uint2* hp = (const uint2*)g_hH;
    for (int e = beg; e < end; e += 32) {
        int myj = (e + lane < end) ? g_srcperm[e + lane] : 0;
        int cnt = min(32, end - e);
#pragma unroll 4
        for (int kk = 0; kk < cnt; kk++) {
            int j = __shfl_sync(0xffffffffu, myj, kk);
            uint2 v = hp[j * 32 + lane];
            float2 f01 = __half22float2(*(__half2*)&v.x);
            float2 f23 = __half22float2(*(__half2*)&v.y);
            float4 m = make_float4(f01.x, f01.y, f23.x, f23.y);
            s1.x += m.x; s1.y += m.y; s1.z += m.z; s1.w += m.w;
            s2.x += m.x * m.x; s2.y += m.y * m.y; s2.z += m.z * m.z; s2.w += m.w * m.w;
            mn.x = fminf(mn.x, m.x); mn.y = fminf(mn.y, m.y); mn.z = fminf(mn.z, m.z); mn.w = fminf(mn.w, m.w);
            mx.x = fmaxf(mx.x, m.x); mx.y = fmaxf(mx.y, m.y); mx.z = fmaxf(mx.z, m.z); mx.w = fmaxf(mx.w, m.w);
        }
    }
    float dinv = g_dinv[warp];
    float4 mean, sd;
    mean.x = s1.x * dinv; mean.y = s1.y * dinv; mean.z = s1.z * dinv; mean.w = s1.w * dinv;
    sd.x = sqrtf(fmaxf(s2.x * dinv - mean.x * mean.x, 0.f) + EPSF);
    sd.y = sqrtf(fmaxf(s2.y * dinv - mean.y * mean.y, 0.f) + EPSF);
    sd.z = sqrtf(fmaxf(s2.z * dinv - mean.z * mean.z, 0.f) + EPSF);
    sd.w = sqrtf(fmaxf(s2.w * dinv - mean.w * mean.w, 0.f) + EPSF);
    if (beg == end) { mn = f4zero(); mx = f4zero(); }

    float amp = g_amp[warp], att = g_att[warp];
    float4 ag[4] = { mean, mn, mx, sd };
    unsigned* base = g_aggsH + (size_t)warp * 768;   // uints; 256 per slab
#pragma unroll
    for (int s = 0; s < 3; s++) {
        float sc = (s == 0) ? 1.f : ((s == 1) ? amp : att);
#pragma unroll
        for (int a = 0; a < 4; a++) {
            uint2 w;
            w.x = packh2(ag[a].x * sc, ag[a].y * sc);
            w.y = packh2(ag[a].z * sc, ag[a].w * sc);
            *(uint2*)&base[s * 256 + a * 64 + lane * 2] = w;
        }
    }
}

// ---------------- FP16 tensor-core GEMM (m16n8k16), 3-stage cp.async pipeline ----------------
// C[128 x 128] per block; 8 warps each 64x32. A = g_aggsH (pre-scaled fp16), B = WtH.
#define BM 128
#define BK 16
#define SSTH 12             // words per row (8 used + 4 pad)
#define NCHUNK 96           // 1536 / BK
#define STAGES 3

__global__ __launch_bounds__(256, 2) void k_gemm(const __half* __restrict__ WtH,
                                                 const float* __restrict__ bl) {
    __shared__ unsigned sA[STAGES][BM * SSTH];
    __shared__ unsigned sB[STAGES][DD * SSTH];
    __shared__ float sBias[DD];
    __shared__ float sSum[DD], sSq[DD];

    int bm = blockIdx.x * BM;
    int tid = threadIdx.x;
    int lane = tid & 31;
    int warp = tid >> 5;
    int g = lane >> 2;
    int t = lane & 3;
    int m_base = (warp >> 2) * 64;
    int n_base = (warp & 3) * 32;

    if (tid < DD) {
        sBias[tid] = bl[tid];
        sSum[tid] = 0.f;
        sSq[tid] = 0.f;
    }
    __syncthreads();

    float acc[4][4][4];
#pragma unroll
    for (int i = 0; i < 4; i++)
#pragma unroll
        for (int j = 0; j < 4; j++)
#pragma unroll
            for (int c = 0; c < 4; c++) acc[i][j][c] = 0.f;

    const int row = tid >> 1;       // 0..127
    const int seg = tid & 1;        // 16B segment within the 32B chunk-row
    const int aOK = (bm + row) < NN ? 16 : 0;
    const unsigned* aSrc = g_aggsH + (size_t)(bm + row) * 768 + seg * 4;
    const __half* bSrc = WtH + (size_t)row * 1536 + seg * 8;

    auto cpAB = [&](int chunk, int buf) {
        unsigned da = (unsigned)__cvta_generic_to_shared(&sA[buf][row * SSTH + seg * 4]);
        cp_async16p(da, aSrc + chunk * 8, aOK);
        unsigned db = (unsigned)__cvta_generic_to_shared(&sB[buf][row * SSTH + seg * 4]);
        cp_async16(db, bSrc + chunk * BK);
    };
    auto mmaChunk = [&](int buf) {
        unsigned bfrag[4][2];
#pragma unroll
        for (int j = 0; j < 4; j++) {
            int n = n_base + j * 8 + g;
            bfrag[j][0] = sB[buf][n * SSTH + t];
            bfrag[j][1] = sB[buf][n * SSTH + t + 4];
        }
#pragma unroll
        for (int i = 0; i < 4; i++) {
            int m0 = m_base + i * 16 + g;
            unsigned a0 = sA[buf][m0 * SSTH + t];
            unsigned a1 = sA[buf][(m0 + 8) * SSTH + t];
            unsigned a2 = sA[buf][m0 * SSTH + t + 4];
            unsigned a3 = sA[buf][(m0 + 8) * SSTH + t + 4];
#pragma unroll
            for (int j = 0; j < 4; j++) {
                asm volatile(
                    "mma.sync.aligned.m16n8k16.row.col.f32.f16.f16.f32 "
                    "{%0,%1,%2,%3}, {%4,%5,%6,%7}, {%8,%9}, {%0,%1,%2,%3};"
                    : "+f"(acc[i][j][0]), "+f"(acc[i][j][1]),
                      "+f"(acc[i][j][2]), "+f"(acc[i][j][3])
                    : "r"(a0), "r"(a1), "r"(a2), "r"(a3),
                      "r"(bfrag[j][0]), "r"(bfrag[j][1]));
            }
        }
    };

    // prologue: prefetch chunks 0,1
    cpAB(0, 0); cp_commit();
    cpAB(1, 1); cp_commit();

    for (int c = 0; c < NCHUNK; c++) {
        cp_wait1();                  // group c complete
        __syncthreads();
        if (c + 2 < NCHUNK) {
            cpAB(c + 2, (c + 2) % STAGES);
            cp_commit();
        }
        mmaChunk(c % STAGES);
    }

    // epilogue: bias + store
#pragma unroll
    for (int i = 0; i < 4; i++) {
        int r0 = bm + m_base + i * 16 + g;
        int r1 = r0 + 8;
#pragma unroll
        for (int j = 0; j < 4; j++) {
            int col = n_base + j * 8 + t * 2;
            float bx = sBias[col], by = sBias[col + 1];
            acc[i][j][0] += bx; acc[i][j][1] += by;
            acc[i][j][2] += bx; acc[i][j][3] += by;
            if (r0 < NN)
                *(float2*)&g_out[(size_t)r0 * DD + col] = make_float2(acc[i][j][0], acc[i][j][1]);
            if (r1 < NN)
                *(float2*)&g_out[(size_t)r1 * DD + col] = make_float2(acc[i][j][2], acc[i][j][3]);
        }
    }

    // fused BN stats: per-column sum/sumsq over valid rows
#pragma unroll
    for (int j = 0; j < 4; j++)
#pragma unroll
        for (int c2 = 0; c2 < 2; c2++) {
            int col = n_base + j * 8 + t * 2 + c2;
            float s = 0.f, q = 0.f;
#pragma unroll
            for (int i = 0; i < 4; i++) {
                int r0 = bm + m_base + i * 16 + g;
                float v0 = acc[i][j][c2];
                float v1 = acc[i][j][2 + c2];
                if (r0 < NN) { s += v0; q += v0 * v0; }
                if (r0 + 8 < NN) { s += v1; q += v1 * v1; }
            }
#pragma unroll
            for (int m = 4; m <= 16; m <<= 1) {
                s += __shfl_xor_sync(0xffffffffu, s, m);
                q += __shfl_xor_sync(0xffffffffu, q, m);
            }
            if (g == 0) {
                atomicAdd(&sSum[col], s);
                atomicAdd(&sSq[col], q);
            }
        }
    __syncthreads();
    if (tid < DD) {
        atomicAdd(&g_bnsum[tid], sSum[tid]);
        atomicAdd(&g_bnsq[tid], sSq[tid]);
    }
}

__global__ void k_bnfin(const float* __restrict__ gamma, const float* __restrict__ beta) {
    int f = threadIdx.x;
    float mu = g_bnsum[f] / (float)NN;
    float var = g_bnsq[f] / (float)NN - mu * mu;
    float rs = rsqrtf(var + EPSF);
    g_mu[f] = mu;
    g_rsg[f] = rs * gamma[f];
    g_bt[f] = beta[f];
}

__global__ void k_bnapply() {
    int t = blockIdx.x * blockDim.x + threadIdx.x;
    if (t >= NN * 32) return;
    int c = (t & 31) * 4;
    float4 o = ((const float4*)g_out)[t];
    float4 h = ((float4*)g_h)[t];
    o.x = fmaxf((o.x - g_mu[c + 0]) * g_rsg[c + 0] + g_bt[c + 0], 0.f) + h.x;
    o.y = fmaxf((o.y - g_mu[c + 1]) * g_rsg[c + 1] + g_bt[c + 1], 0.f) + h.y;
    o.z = fmaxf((o.z - g_mu[c + 2]) * g_rsg[c + 2] + g_bt[c + 2], 0.f) + h.z;
    o.w = fmaxf((o.w - g_mu[c + 3]) * g_rsg[c + 3] + g_bt[c + 3], 0.f) + h.w;
    ((float4*)g_h)[t] = o;
    ((uint2*)g_hH)[t] = make_uint2(packh2(o.x, o.y), packh2(o.z, o.w));
}

// ---------------- pooling + MLP ----------------
__global__ void k_pool() {
    int warp = (blockIdx.x * blockDim.x + threadIdx.x) >> 5;
    int lane = threadIdx.x & 31;
    if (warp >= NG) return;
    int beg = g_goff[warp], end = g_goff[warp + 1];
    float4 s = f4zero();
    const float4* hp = (const float4*)g_h;
    for (int r = beg; r < end; r++) {
        float4 v = hp[r * 32 + lane];
        s.x += v.x; s.y += v.y; s.z += v.z; s.w += v.w;
    }
    float inv = 1.f / (float)max(end - beg, 1);
    s.x *= inv; s.y *= inv; s.z *= inv; s.w *= inv;
    ((float4*)g_pool)[warp * 32 + lane] = s;
}

__global__ void k_mlp(const float* __restrict__ W1, const float* __restrict__ b1,
                      const float* __restrict__ W2, const float* __restrict__ b2,
                      const float* __restrict__ W3, const float* __restrict__ b3,
                      float* __restrict__ out) {
    __shared__ float sg[DD], sz1[64], sz2[32];
    int gid = blockIdx.x;
    int tid = threadIdx.x;      // 128
    sg[tid] = g_pool[gid * DD + tid];
    __syncthreads();
    if (tid < 64) {
        float a = b1[tid];
        for (int k = 0; k < DD; k++) a += sg[k] * W1[k * 64 + tid];
        sz1[tid] = fmaxf(a, 0.f);
    }
    __syncthreads();
    if (tid < 32) {
        float a = b2[tid];
        for (int k = 0; k < 64; k++) a += sz1[k] * W2[k * 32 + tid];
        sz2[tid] = fmaxf(a, 0.f);
    }
    __syncthreads();
    if (tid < NT) {
        float a = b3[tid];
        for (int k = 0; k < 32; k++) a += sz2[k] * W3[k * NT + tid];
        out[gid * NT + tid] = a;
    }
}

// ---------------- launch ----------------
extern "C" void kernel_launch(void* const* d_in, const int* in_sizes, int n_in,
                              void* d_out, int out_size) {
    const float* x      = (const float*)d_in[0];
    const int*   ei     = (const int*)d_in[1];
    const int*   batch  = (const int*)d_in[2];
    const float* emb_W  = (const float*)d_in[3];
    const float* emb_b  = (const float*)d_in[4];
    const float* conv_W = (const float*)d_in[5];
    const float* conv_b = (const float*)d_in[6];
    const float* bng    = (const float*)d_in[7];
    const float* bnb    = (const float*)d_in[8];
    const float* W1     = (const float*)d_in[9];
    const float* b1     = (const float*)d_in[10];
    const float* W2     = (const float*)d_in[11];
    const float* b2     = (const float*)d_in[12];
    const float* W3     = (const float*)d_in[13];
    const float* b3     = (const float*)d_in[14];
    float* out = (float*)d_out;

    k_zero<<<(NN + 255) / 256, 256>>>();
    k_hist<<<(NE + 255) / 256, 256>>>(ei, batch);
    k_scan<<<1, 1024>>>();
    k_delta<<<(NN + 255) / 256, 256>>>();
    k_scalars<<<(NN + 255) / 256, 256>>>();
    k_scatter<<<(NE + 255) / 256, 256>>>(ei);
    k_emb<<<(NN * 32 + 255) / 256, 256>>>(x, emb_W, emb_b);
    k_wprep<<<(NL * 1536 * DD + 255) / 256, 256>>>(conv_W);

    __half* g_WtH_ptr;
    cudaGetSymbolAddress((void**)&g_WtH_ptr, g_WtH);

    for (int l = 0; l < NL; l++) {
        k_agg<<<(NN * 32 + 255) / 256, 256>>>();
        k_gemm<<<(NN + BM - 1) / BM, 256>>>(g_WtH_ptr + (size_t)l * DD * 1536,
                                            conv_b + (size_t)l * DD);
        k_bnfin<<<1, DD>>>(bng + (size_t)l * DD, bnb + (size_t)l * DD);
        k_bnapply<<<(NN * 32 + 255) / 256, 256>>>();
    }

    k_pool<<<(NG * 32 + 255) / 256, 256>>>();
    k_mlp<<<NG, DD>>>(W1, b1, W2, b2, W3, b3, out);
}

// round 11
// speedup vs baseline: 1.7041x; 1.0242x over previous
#include <cuda_runtime.h>
#include <cuda_fp16.h>
#include <math.h>

#define NN 50000
#define NE 600000
#define DD 128
#define NL 4
#define NG 512
#define NT 10
#define EPSF 1e-5f

// ---------------- scratch (static device allocations) ----------------
__device__ int   g_deg[NN];
__device__ int   g_rowptr[NN + 1];
__device__ int   g_cursor[NN];
__device__ int   g_srcperm[NE];
__device__ float g_amp[NN], g_att[NN], g_dinv[NN];
__device__ float g_delta_acc;
__device__ float g_h[NN * DD];
__device__ unsigned g_hH[NN * DD / 2];              // fp16 mirror of g_h (packed half2)
__device__ unsigned g_aggsH[(size_t)NN * 768];      // [N][1536] halves: [aggs|amp*aggs|att*aggs]
__device__ float g_out[NN * DD];
__device__ float g_bnsum[DD], g_bnsq[DD];
__device__ int   g_gcnt[NG];
__device__ int   g_goff[NG + 1];
__device__ __half g_WtH[(size_t)NL * DD * 1536];    // W transposed fp16: [l][n][k]

// ---------------- small helpers ----------------
__device__ __forceinline__ float4 f4zero() { return make_float4(0.f, 0.f, 0.f, 0.f); }

__device__ __forceinline__ unsigned packh2(float a, float b) {
    __half2 h = __floats2half2_rn(a, b);
    return *(unsigned*)&h;
}

__device__ __forceinline__ void cp_async16(unsigned smem_addr, const void* gptr) {
    asm volatile("cp.async.cg.shared.global [%0], [%1], 16;" :: "r"(smem_addr), "l"(gptr));
}
__device__ __forceinline__ void cp_async16p(unsigned smem_addr, const void* gptr, int szbytes) {
    asm volatile("cp.async.cg.shared.global [%0], [%1], 16, %2;"
                 :: "r"(smem_addr), "l"(gptr), "r"(szbytes));
}
__device__ __forceinline__ void cp_commit() { asm volatile("cp.async.commit_group;"); }
__device__ __forceinline__ void cp_wait0() { asm volatile("cp.async.wait_group 0;"); }
__device__ __forceinline__ void cp_wait2() { asm volatile("cp.async.wait_group 2;"); }

// ---------------- setup kernels ----------------
__global__ void k_zero() {
    int i = blockIdx.x * blockDim.x + threadIdx.x;
    if (i < NN) { g_deg[i] = 0; g_cursor[i] = 0; }
    if (i < NG) g_gcnt[i] = 0;
    if (i == 0) g_delta_acc = 0.f;
}

__global__ void k_hist(const int* __restrict__ ei, const int* __restrict__ batch) {
    int e = blockIdx.x * blockDim.x + threadIdx.x;
    if (e < NE) atomicAdd(&g_deg[ei[NE + e]], 1);     // dst row
    if (e < NN) atomicAdd(&g_gcnt[batch[e]], 1);
}

__global__ void k_scan() {
    __shared__ int s[1024];
    int t = threadIdx.x;
    const int C = (NN + 1023) / 1024;
    int base = t * C;
    int acc = 0;
    for (int c = 0; c < C; c++) { int i = base + c; if (i < NN) acc += g_deg[i]; }
    s[t] = acc;
    __syncthreads();
    for (int d = 1; d < 1024; d <<= 1) {
        int add = (t >= d) ? s[t - d] : 0;
        __syncthreads();
        s[t] += add;
        __syncthreads();
    }
    int off = s[t] - acc;
    for (int c = 0; c < C; c++) { int i = base + c; if (i < NN) { g_rowptr[i] = off; off += g_deg[i]; } }
    if (t == 0) g_rowptr[NN] = NE;
    __syncthreads();
    int v = (t < NG) ? g_gcnt[t] : 0;
    s[t] = v;
    __syncthreads();
    for (int d = 1; d < 1024; d <<= 1) {
        int add = (t >= d) ? s[t - d] : 0;
        __syncthreads();
        s[t] += add;
        __syncthreads();
    }
    if (t < NG) g_goff[t] = s[t] - v;
    if (t == 0) g_goff[NG] = NN;
}

__global__ void k_delta() {
    int i = blockIdx.x * blockDim.x + threadIdx.x;
    float v = (i < NN) ? log1pf((float)g_deg[i]) : 0.f;
    for (int o = 16; o; o >>= 1) v += __shfl_down_sync(0xffffffffu, v, o);
    __shared__ float ws[8];
    if ((threadIdx.x & 31) == 0) ws[threadIdx.x >> 5] = v;
    __syncthreads();
    if (threadIdx.x < 8) {
        v = ws[threadIdx.x];
        for (int o = 4; o; o >>= 1) v += __shfl_down_sync(0xffu, v, o);
        if (threadIdx.x == 0) atomicAdd(&g_delta_acc, v);
    }
}

__global__ void k_scalars() {
    int i = blockIdx.x * blockDim.x + threadIdx.x;
    if (i >= NN) return;
    float deg = (float)g_deg[i];
    float d = fmaxf(deg, 1.f);
    float ld = log1pf(d);
    float delta = g_delta_acc / (float)NN;
    g_amp[i] = ld / delta;
    g_att[i] = delta / ld;
    g_dinv[i] = 1.f / d;
}

__global__ void k_scatter(const int* __restrict__ ei) {
    int e = blockIdx.x * blockDim.x + threadIdx.x;
    if (e >= NE) return;
    int dst = ei[NE + e];
    int p = atomicAdd(&g_cursor[dst], 1);
    g_srcperm[g_rowptr[dst] + p] = ei[e];
}

__global__ void k_emb(const float* __restrict__ x, const float* __restrict__ W,
                      const float* __restrict__ b) {
    int t = blockIdx.x * blockDim.x + threadIdx.x;
    int i = t >> 5, c = t & 31;
    if (i >= NN) return;
    float x0 = x[i * 3 + 0], x1 = x[i * 3 + 1], x2 = x[i * 3 + 2];
    float4 w0 = *(const float4*)&W[0 * DD + c * 4];
    float4 w1 = *(const float4*)&W[1 * DD + c * 4];
    float4 w2 = *(const float4*)&W[2 * DD + c * 4];
    float4 bb = *(const float4*)&b[c * 4];
    float4 h;
    h.x = bb.x + x0 * w0.x + x1 * w1.x + x2 * w2.x;
    h.y = bb.y + x0 * w0.y + x1 * w1.y + x2 * w2.y;
    h.z = bb.z + x0 * w0.z + x1 * w1.z + x2 * w2.z;
    h.w = bb.w + x0 * w0.w + x1 * w1.w + x2 * w2.w;
    ((float4*)g_h)[i * 32 + c] = h;
    ((uint2*)g_hH)[i * 32 + c] = make_uint2(packh2(h.x, h.y), packh2(h.z, h.w));
}

// Transpose + fp16-convert conv weights: g_WtH[l][n][k] = half(W[l][k][n])
__global__ void k_wprep(const float* __restrict__ conv_W) {
    int t = blockIdx.x * blockDim.x + threadIdx.x;
    if (t >= NL * 1536 * DD) return;
    int l = t / (1536 * DD);
    int r = t - l * (1536 * DD);
    int k = r >> 7;           // 0..1535
    int n = r & 127;          // coalesced read along n
    g_WtH[((size_t)l * DD + n) * 1536 + k] = __float2half_rn(conv_W[t]);
}

// ---------------- per-layer kernels ----------------
// warp per node; gathers fp16 h rows; writes pre-scaled fp16 A matrix (3 slabs).
__global__ void k_agg() {
    if (blockIdx.x == 0 && threadIdx.x < DD) {    // reset BN accumulators for this layer
        g_bnsum[threadIdx.x] = 0.f;
        g_bnsq[threadIdx.x] = 0.f;
    }
    int warp = (blockIdx.x * blockDim.x + threadIdx.x) >> 5;
    int lane = threadIdx.x & 31;
    if (warp >= NN) return;
    int beg = g_rowptr[warp], end = g_rowptr[warp + 1];
    float4 s1 = f4zero(), s2 = f4zero();
    float4 mn = make_float4(INFINITY, INFINITY, INFINITY, INFINITY);
    float4 mx = make_float4(-INFINITY, -INFINITY, -INFINITY, -INFINITY);
    const uint2* hp = (const uint2*)g_hH;
    for (int e = beg; e < end; e += 32) {
        int myj = (e + lane < end) ? g_srcperm[e + lane] : 0;
        int cnt = min(32, end - e);
#pragma unroll 4
        for (int kk = 0; kk < cnt; kk++) {
            int j = __shfl_sync(0xffffffffu, myj, kk);
            uint2 v = hp[j * 32 + lane];
            float2 f01 = __half22float2(*(__half2*)&v.x);
            float2 f23 = __half22float2(*(__half2*)&v.y);
            float4 m = make_float4(f01.x, f01.y, f23.x, f23.y);
            s1.x += m.x; s1.y += m.y; s1.z += m.z; s1.w += m.w;
            s2.x += m.x * m.x; s2.y += m.y * m.y; s2.z += m.z * m.z; s2.w += m.w * m.w;
            mn.x = fminf(mn.x, m.x); mn.y = fminf(mn.y, m.y); mn.z = fminf(mn.z, m.z); mn.w = fminf(mn.w, m.w);
            mx.x = fmaxf(mx.x, m.x); mx.y = fmaxf(mx.y, m.y); mx.z = fmaxf(mx.z, m.z); mx.w = fmaxf(mx.w, m.w);
        }
    }
    float dinv = g_dinv[warp];
    float4 mean, sd;
    mean.x = s1.x * dinv; mean.y = s1.y * dinv; mean.z = s1.z * dinv; mean.w = s1.w * dinv;
    sd.x = sqrtf(fmaxf(s2.x * dinv - mean.x * mean.x, 0.f) + EPSF);
    sd.y = sqrtf(fmaxf(s2.y * dinv - mean.y * mean.y, 0.f) + EPSF);
    sd.z = sqrtf(fmaxf(s2.z * dinv - mean.z * mean.z, 0.f) + EPSF);
    sd.w = sqrtf(fmaxf(s2.w * dinv - mean.w * mean.w, 0.f) + EPSF);
    if (beg == end) { mn = f4zero(); mx = f4zero(); }

    float amp = g_amp[warp], att = g_att[warp];
    float4 ag[4] = { mean, mn, mx, sd };
    unsigned* base = g_aggsH + (size_t)warp * 768;   // uints; 256 per slab
#pragma unroll
    for (int s = 0; s < 3; s++) {
        float sc = (s == 0) ? 1.f : ((s == 1) ? amp : att);
#pragma unroll
        for (int a = 0; a < 4; a++) {
            uint2 w;
            w.x = packh2(ag[a].x * sc, ag[a].y * sc);
            w.y = packh2(ag[a].z * sc, ag[a].w * sc);
            *(uint2*)&base[s * 256 + a * 64 + lane * 2] = w;
        }
    }
}

// ---------------- FP16 tensor-core GEMM (m16n8k16), 4-stage cp.async pipeline ----------------
// C[128 x 128] per block; 8 warps each 64x32. A = g_aggsH (pre-scaled fp16), B = WtH.
#define BM 128
#define BK 16
#define SSTH 12             // words per row (8 used + 4 pad)
#define NCHUNK 96           // 1536 / BK
#define STAGES 4

__global__ __launch_bounds__(256, 2) void k_gemm(const __half* __restrict__ WtH,
                                                 const float* __restrict__ bl) {
    __shared__ unsigned sA[STAGES][BM * SSTH];
    __shared__ unsigned sB[STAGES][DD * SSTH];
    __shared__ float sBias[DD];
    __shared__ float sSum[DD], sSq[DD];

    int bm = blockIdx.x * BM;
    int tid = threadIdx.x;
    int lane = tid & 31;
    int warp = tid >> 5;
    int g = lane >> 2;
    int t = lane & 3;
    int m_base = (warp >> 2) * 64;
    int n_base = (warp & 3) * 32;

    if (tid < DD) {
        sBias[tid] = bl[tid];
        sSum[tid] = 0.f;
        sSq[tid] = 0.f;
    }
    __syncthreads();

    float acc[4][4][4];
#pragma unroll
    for (int i = 0; i < 4; i++)
#pragma unroll
        for (int j = 0; j < 4; j++)
#pragma unroll
            for (int c = 0; c < 4; c++) acc[i][j][c] = 0.f;

    const int row = tid >> 1;       // 0..127
    const int seg = tid & 1;        // 16B segment within the 32B chunk-row
    const int aOK = (bm + row) < NN ? 16 : 0;
    const unsigned* aSrc = g_aggsH + (size_t)(bm + row) * 768 + seg * 4;
    const __half* bSrc = WtH + (size_t)row * 1536 + seg * 8;

    auto cpAB = [&](int chunk, int buf) {
        unsigned da = (unsigned)__cvta_generic_to_shared(&sA[buf][row * SSTH + seg * 4]);
        cp_async16p(da, aSrc + chunk * 8, aOK);
        unsigned db = (unsigned)__cvta_generic_to_shared(&sB[buf][row * SSTH + seg * 4]);
        cp_async16(db, bSrc + chunk * BK);
    };
    auto mmaChunk = [&](int buf) {
        unsigned bfrag[4][2];
#pragma unroll
        for (int j = 0; j < 4; j++) {
            int n = n_base + j * 8 + g;
            bfrag[j][0] = sB[buf][n * SSTH + t];
            bfrag[j][1] = sB[buf][n * SSTH + t + 4];
        }
#pragma unroll
        for (int i = 0; i < 4; i++) {
            int m0 = m_base + i * 16 + g;
            unsigned a0 = sA[buf][m0 * SSTH + t];
            unsigned a1 = sA[buf][(m0 + 8) * SSTH + t];
            unsigned a2 = sA[buf][m0 * SSTH + t + 4];
            unsigned a3 = sA[buf][(m0 + 8) * SSTH + t + 4];
#pragma unroll
            for (int j = 0; j < 4; j++) {
                asm volatile(
                    "mma.sync.aligned.m16n8k16.row.col.f32.f16.f16.f32 "
                    "{%0,%1,%2,%3}, {%4,%5,%6,%7}, {%8,%9}, {%0,%1,%2,%3};"
                    : "+f"(acc[i][j][0]), "+f"(acc[i][j][1]),
                      "+f"(acc[i][j][2]), "+f"(acc[i][j][3])
                    : "r"(a0), "r"(a1), "r"(a2), "r"(a3),
                      "r"(bfrag[j][0]), "r"(bfrag[j][1]));
            }
        }
    };

    // prologue: prefetch chunks 0,1,2
    cpAB(0, 0); cp_commit();
    cpAB(1, 1); cp_commit();
    cpAB(2, 2); cp_commit();

    for (int c = 0; c < NCHUNK; c++) {
        if (c + 3 < NCHUNK) cp_wait2(); else cp_wait0();
        __syncthreads();
        if (c + 3 < NCHUNK) {
            cpAB(c + 3, (c + 3) % STAGES);
            cp_commit();
        }
        mmaChunk(c % STAGES);
    }

    // epilogue: bias + store
#pragma unroll
    for (int i = 0; i < 4; i++) {
        int r0 = bm + m_base + i * 16 + g;
        int r1 = r0 + 8;
#pragma unroll
        for (int j = 0; j < 4; j++) {
            int col = n_base + j * 8 + t * 2;
            float bx = sBias[col], by = sBias[col + 1];
            acc[i][j][0] += bx; acc[i][j][1] += by;
            acc[i][j][2] += bx; acc[i][j][3] += by;
            if (r0 < NN)
                *(float2*)&g_out[(size_t)r0 * DD + col] = make_float2(acc[i][j][0], acc[i][j][1]);
            if (r1 < NN)
                *(float2*)&g_out[(size_t)r1 * DD + col] = make_float2(acc[i][j][2], acc[i][j][3]);
        }
    }

    // fused BN stats: per-column sum/sumsq over valid rows
#pragma unroll
    for (int j = 0; j < 4; j++)
#pragma unroll
        for (int c2 = 0; c2 < 2; c2++) {
            int col = n_base + j * 8 + t * 2 + c2;
            float s = 0.f, q = 0.f;
#pragma unroll
            for (int i = 0; i < 4; i++) {
                int r0 = bm + m_base + i * 16 + g;
                float v0 = acc[i][j][c2];
                float v1 = acc[i][j][2 + c2];
                if (r0 < NN) { s += v0; q += v0 * v0; }
                if (r0 + 8 < NN) { s += v1; q += v1 * v1; }
            }
#pragma unroll
            for (int m = 4; m <= 16; m <<= 1) {
                s += __shfl_xor_sync(0xffffffffu, s, m);
                q += __shfl_xor_sync(0xffffffffu, q, m);
            }
            if (g == 0) {
                atomicAdd(&sSum[col], s);
                atomicAdd(&sSq[col], q);
            }
        }
    __syncthreads();
    if (tid < DD) {
        atomicAdd(&g_bnsum[tid], sSum[tid]);
        atomicAdd(&g_bnsq[tid], sSq[tid]);
    }
}

// BN apply with inline param computation (bnfin folded in) + residual + fp16 mirror
__global__ void k_bnapply(const float* __restrict__ gamma, const float* __restrict__ beta) {
    int t = blockIdx.x * blockDim.x + threadIdx.x;
    if (t >= NN * 32) return;
    int c = (t & 31) * 4;
    float mu[4], rsg[4], bt[4];
#pragma unroll
    for (int u = 0; u < 4; u++) {
        float m = g_bnsum[c + u] / (float)NN;
        float var = g_bnsq[c + u] / (float)NN - m * m;
        mu[u] = m;
        rsg[u] = rsqrtf(var + EPSF) * gamma[c + u];
        bt[u] = beta[c + u];
    }
    float4 o = ((const float4*)g_out)[t];
    float4 h = ((float4*)g_h)[t];
    o.x = fmaxf((o.x - mu[0]) * rsg[0] + bt[0], 0.f) + h.x;
    o.y = fmaxf((o.y - mu[1]) * rsg[1] + bt[1], 0.f) + h.y;
    o.z = fmaxf((o.z - mu[2]) * rsg[2] + bt[2], 0.f) + h.z;
    o.w = fmaxf((o.w - mu[3]) * rsg[3] + bt[3], 0.f) + h.w;
    ((float4*)g_h)[t] = o;
    ((uint2*)g_hH)[t] = make_uint2(packh2(o.x, o.y), packh2(o.z, o.w));
}

// ---------------- fused pooling + MLP: one block per graph ----------------
__global__ void k_poolmlp(const float* __restrict__ W1, const float* __restrict__ b1,
                          const float* __restrict__ W2, const float* __restrict__ b2,
                          const float* __restrict__ W3, const float* __restrict__ b3,
                          float* __restrict__ out) {
    __shared__ float sg[DD], sz1[64], sz2[32];
    int gid = blockIdx.x;
    int tid = threadIdx.x;      // 128 threads, one per feature
    int beg = g_goff[gid], end = g_goff[gid + 1];
    float s = 0.f;
    for (int r = beg; r < end; r++) s += g_h[(size_t)r * DD + tid];
    sg[tid] = s / (float)max(end - beg, 1);
    __syncthreads();
    if (tid < 64) {
        float a = b1[tid];
        for (int k = 0; k < DD; k++) a += sg[k] * W1[k * 64 + tid];
        sz1[tid] = fmaxf(a, 0.f);
    }
    __syncthreads();
    if (tid < 32) {
        float a = b2[tid];
        for (int k = 0; k < 64; k++) a += sz1[k] * W2[k * 32 + tid];
        sz2[tid] = fmaxf(a, 0.f);
    }
    __syncthreads();
    if (tid < NT) {
        float a = b3[tid];
        for (int k = 0; k < 32; k++) a += sz2[k] * W3[k * NT + tid];
        out[gid * NT + tid] = a;
    }
}

// ---------------- launch ----------------
extern "C" void kernel_launch(void* const* d_in, const int* in_sizes, int n_in,
                              void* d_out, int out_size) {
    const float* x      = (const float*)d_in[0];
    const int*   ei     = (const int*)d_in[1];
    const int*   batch  = (const int*)d_in[2];
    const float* emb_W  = (const float*)d_in[3];
    const float* emb_b  = (const float*)d_in[4];
    const float* conv_W = (const float*)d_in[5];
    const float* conv_b = (const float*)d_in[6];
    const float* bng    = (const float*)d_in[7];
    const float* bnb    = (const float*)d_in[8];
    const float* W1     = (const float*)d_in[9];
    const float* b1     = (const float*)d_in[10];
    const float* W2     = (const float*)d_in[11];
    const float* b2     = (const float*)d_in[12];
    const float* W3     = (const float*)d_in[13];
    const float* b3     = (const float*)d_in[14];
    float* out = (float*)d_out;

    k_zero<<<(NN + 255) / 256, 256>>>();
    k_hist<<<(NE + 255) / 256, 256>>>(ei, batch);
    k_scan<<<1, 1024>>>();
    k_delta<<<(NN + 255) / 256, 256>>>();
    k_scalars<<<(NN + 255) / 256, 256>>>();
    k_scatter<<<(NE + 255) / 256, 256>>>(ei);
    k_emb<<<(NN * 32 + 255) / 256, 256>>>(x, emb_W, emb_b);
    k_wprep<<<(NL * 1536 * DD + 255) / 256, 256>>>(conv_W);

    __half* g_WtH_ptr;
    cudaGetSymbolAddress((void**)&g_WtH_ptr, g_WtH);

    for (int l = 0; l < NL; l++) {
        k_agg<<<(NN * 32 + 255) / 256, 256>>>();
        k_gemm<<<(NN + BM - 1) / BM, 256>>>(g_WtH_ptr + (size_t)l * DD * 1536,
                                            conv_b + (size_t)l * DD);
        k_bnapply<<<(NN * 32 + 255) / 256, 256>>>(bng + (size_t)l * DD, bnb + (size_t)l * DD);
    }

    k_poolmlp<<<NG, DD>>>(W1, b1, W2, b2, W3, b3, out);
}

// round 12
// speedup vs baseline: 1.7321x; 1.0164x over previous
#include <cuda_runtime.h>
#include <cuda_fp16.h>
#include <math.h>

#define NN 50000
#define NE 600000
#define DD 128
#define NL 4
#define NG 512
#define NT 10
#define EPSF 1e-5f

// ---------------- scratch (static device allocations) ----------------
__device__ int   g_deg[NN];
__device__ int   g_rowptr[NN + 1];
__device__ int   g_cursor[NN];
__device__ int   g_srcperm[NE];
__device__ float g_amp[NN], g_att[NN], g_dinv[NN];
__device__ float g_delta_acc;
__device__ float g_h[NN * DD];
__device__ unsigned g_hH[NN * DD / 2];              // fp16 mirror of g_h (packed half2)
__device__ unsigned g_aggsH[(size_t)NN * 768];      // [N][1536] halves: [aggs|amp*aggs|att*aggs]
__device__ float g_out[NN * DD];
__device__ float g_bnsum[DD], g_bnsq[DD];
__device__ int   g_gcnt[NG];
__device__ int   g_goff[NG + 1];
__device__ __half g_WtH[(size_t)NL * DD * 1536];    // W transposed fp16: [l][n][k]

// ---------------- small helpers ----------------
__device__ __forceinline__ float4 f4zero() { return make_float4(0.f, 0.f, 0.f, 0.f); }

__device__ __forceinline__ unsigned packh2(float a, float b) {
    __half2 h = __floats2half2_rn(a, b);
    return *(unsigned*)&h;
}

__device__ __forceinline__ void cp_async16(unsigned smem_addr, const void* gptr) {
    asm volatile("cp.async.cg.shared.global [%0], [%1], 16;" :: "r"(smem_addr), "l"(gptr));
}
__device__ __forceinline__ void cp_async16p(unsigned smem_addr, const void* gptr, int szbytes) {
    asm volatile("cp.async.cg.shared.global [%0], [%1], 16, %2;"
                 :: "r"(smem_addr), "l"(gptr), "r"(szbytes));
}
__device__ __forceinline__ void cp_commit() { asm volatile("cp.async.commit_group;"); }
__device__ __forceinline__ void cp_wait0() { asm volatile("cp.async.wait_group 0;"); }

__device__ __forceinline__ void ldsm_x4(unsigned& r0, unsigned& r1, unsigned& r2, unsigned& r3,
                                        unsigned addr) {
    asm volatile("ldmatrix.sync.aligned.m8n8.x4.shared.b16 {%0,%1,%2,%3}, [%4];"
                 : "=r"(r0), "=r"(r1), "=r"(r2), "=r"(r3) : "r"(addr));
}

// ---------------- setup kernels ----------------
__global__ void k_zero() {
    int i = blockIdx.x * blockDim.x + threadIdx.x;
    if (i < NN) { g_deg[i] = 0; g_cursor[i] = 0; }
    if (i < NG) g_gcnt[i] = 0;
    if (i == 0) g_delta_acc = 0.f;
}

__global__ void k_hist(const int* __restrict__ ei, const int* __restrict__ batch) {
    int e = blockIdx.x * blockDim.x + threadIdx.x;
    if (e < NE) atomicAdd(&g_deg[ei[NE + e]], 1);     // dst row
    if (e < NN) atomicAdd(&g_gcnt[batch[e]], 1);
}

__global__ void k_scan() {
    __shared__ int s[1024];
    int t = threadIdx.x;
    const int C = (NN + 1023) / 1024;
    int base = t * C;
    int acc = 0;
    for (int c = 0; c < C; c++) { int i = base + c; if (i < NN) acc += g_deg[i]; }
    s[t] = acc;
    __syncthreads();
    for (int d = 1; d < 1024; d <<= 1) {
        int add = (t >= d) ? s[t - d] : 0;
        __syncthreads();
        s[t] += add;
        __syncthreads();
    }
    int off = s[t] - acc;
    for (int c = 0; c < C; c++) { int i = base + c; if (i < NN) { g_rowptr[i] = off; off += g_deg[i]; } }
    if (t == 0) g_rowptr[NN] = NE;
    __syncthreads();
    int v = (t < NG) ? g_gcnt[t] : 0;
    s[t] = v;
    __syncthreads();
    for (int d = 1; d < 1024; d <<= 1) {
        int add = (t >= d) ? s[t - d] : 0;
        __syncthreads();
        s[t] += add;
        __syncthreads();
    }
    if (t < NG) g_goff[t] = s[t] - v;
    if (t == 0) g_goff[NG] = NN;
}

__global__ void k_delta() {
    int i = blockIdx.x * blockDim.x + threadIdx.x;
    float v = (i < NN) ? log1pf((float)g_deg[i]) : 0.f;
    for (int o = 16; o; o >>= 1) v += __shfl_down_sync(0xffffffffu, v, o);
    __shared__ float ws[8];
    if ((threadIdx.x & 31) == 0) ws[threadIdx.x >> 5] = v;
    __syncthreads();
    if (threadIdx.x < 8) {
        v = ws[threadIdx.x];
        for (int o = 4; o; o >>= 1) v += __shfl_down_sync(0xffu, v, o);
        if (threadIdx.x == 0) atomicAdd(&g_delta_acc, v);
    }
}

__global__ void k_scalars() {
    int i = blockIdx.x * blockDim.x + threadIdx.x;
    if (i >= NN) return;
    float deg = (float)g_deg[i];
    float d = fmaxf(deg, 1.f);
    float ld = log1pf(d);
    float delta = g_delta_acc / (float)NN;
    g_amp[i] = ld / delta;
    g_att[i] = delta / ld;
    g_dinv[i] = 1.f / d;
}

__global__ void k_scatter(const int* __restrict__ ei) {
    int e = blockIdx.x * blockDim.x + threadIdx.x;
    if (e >= NE) return;
    int dst = ei[NE + e];
    int p = atomicAdd(&g_cursor[dst], 1);
    g_srcperm[g_rowptr[dst] + p] = ei[e];
}

__global__ void k_emb(const float* __restrict__ x, const float* __restrict__ W,
                      const float* __restrict__ b) {
    int t = blockIdx.x * blockDim.x + threadIdx.x;
    int i = t >> 5, c = t & 31;
    if (i >= NN) return;
    float x0 = x[i * 3 + 0], x1 = x[i * 3 + 1], x2 = x[i * 3 + 2];
    float4 w0 = *(const float4*)&W[0 * DD + c * 4];
    float4 w1 = *(const float4*)&W[1 * DD + c * 4];
    float4 w2 = *(const float4*)&W[2 * DD + c * 4];
    float4 bb = *(const float4*)&b[c * 4];
    float4 h;
    h.x = bb.x + x0 * w0.x + x1 * w1.x + x2 * w2.x;
    h.y = bb.y + x0 * w0.y + x1 * w1.y + x2 * w2.y;
    h.z = bb.z + x0 * w0.z + x1 * w1.z + x2 * w2.z;
    h.w = bb.w + x0 * w0.w + x1 * w1.w + x2 * w2.w;
    ((float4*)g_h)[i * 32 + c] = h;
    ((uint2*)g_hH)[i * 32 + c] = make_uint2(packh2(h.x, h.y), packh2(h.z, h.w));
}

// Transpose + fp16-convert conv weights: g_WtH[l][n][k] = half(W[l][k][n])
__global__ void k_wprep(const float* __restrict__ conv_W) {
    int t = blockIdx.x * blockDim.x + threadIdx.x;
    if (t >= NL * 1536 * DD) return;
    int l = t / (1536 * DD);
    int r = t - l * (1536 * DD);
    int k = r >> 7;           // 0..1535
    int n = r & 127;          // coalesced read along n
    g_WtH[((size_t)l * DD + n) * 1536 + k] = __float2half_rn(conv_W[t]);
}

// ---------------- per-layer kernels ----------------
// warp per node; gathers fp16 h rows; writes pre-scaled fp16 A matrix (3 slabs).
__global__ void k_agg() {
    if (blockIdx.x == 0 && threadIdx.x < DD) {    // reset BN accumulators for this layer
        g_bnsum[threadIdx.x] = 0.f;
        g_bnsq[threadIdx.x] = 0.f;
    }
    int warp = (blockIdx.x * blockDim.x + threadIdx.x) >> 5;
    int lane = threadIdx.x & 31;
    if (warp >= NN) return;
    int beg = g_rowptr[warp], end = g_rowptr[warp + 1];
    float4 s1 = f4zero(), s2 = f4zero();
    float4 mn = make_float4(INFINITY, INFINITY, INFINITY, INFINITY);
    float4 mx = make_float4(-INFINITY, -INFINITY, -INFINITY, -INFINITY);
    const uint2* hp = (const uint2*)g_hH;
    for (int e = beg; e < end; e += 32) {
        int myj = (e + lane < end) ? g_srcperm[e + lane] : 0;
        int cnt = min(32, end - e);
#pragma unroll 4
        for (int kk = 0; kk < cnt; kk++) {
            int j = __shfl_sync(0xffffffffu, myj, kk);
            uint2 v = hp[j * 32 + lane];
            float2 f01 = __half22float2(*(__half2*)&v.x);
            float2 f23 = __half22float2(*(__half2*)&v.y);
            float4 m = make_float4(f01.x, f01.y, f23.x, f23.y);
            s1.x += m.x; s1.y += m.y; s1.z += m.z; s1.w += m.w;
            s2.x += m.x * m.x; s2.y += m.y * m.y; s2.z += m.z * m.z; s2.w += m.w * m.w;
            mn.x = fminf(mn.x, m.x); mn.y = fminf(mn.y, m.y); mn.z = fminf(mn.z, m.z); mn.w = fminf(mn.w, m.w);
            mx.x = fmaxf(mx.x, m.x); mx.y = fmaxf(mx.y, m.y); mx.z = fmaxf(mx.z, m.z); mx.w = fmaxf(mx.w, m.w);
        }
    }
    float dinv = g_dinv[warp];
    float4 mean, sd;
    mean.x = s1.x * dinv; mean.y = s1.y * dinv; mean.z = s1.z * dinv; mean.w = s1.w * dinv;
    sd.x = sqrtf(fmaxf(s2.x * dinv - mean.x * mean.x, 0.f) + EPSF);
    sd.y = sqrtf(fmaxf(s2.y * dinv - mean.y * mean.y, 0.f) + EPSF);
    sd.z = sqrtf(fmaxf(s2.z * dinv - mean.z * mean.z, 0.f) + EPSF);
    sd.w = sqrtf(fmaxf(s2.w * dinv - mean.w * mean.w, 0.f) + EPSF);
    if (beg == end) { mn = f4zero(); mx = f4zero(); }

    float amp = g_amp[warp], att = g_att[warp];
    float4 ag[4] = { mean, mn, mx, sd };
    unsigned* base = g_aggsH + (size_t)warp * 768;   // uints; 256 per slab
#pragma unroll
    for (int s = 0; s < 3; s++) {
        float sc = (s == 0) ? 1.f : ((s == 1) ? amp : att);
#pragma unroll
        for (int a = 0; a < 4; a++) {
            uint2 w;
            w.x = packh2(ag[a].x * sc, ag[a].y * sc);
            w.y = packh2(ag[a].z * sc, ag[a].w * sc);
            *(uint2*)&base[s * 256 + a * 64 + lane * 2] = w;
        }
    }
}

// ---------------- FP16 tensor-core GEMM (m16n8k16), ldmatrix + BK=32, 2-stage ----------------
// C[128 x 128] per block; 8 warps each 64x32. A = g_aggsH (pre-scaled fp16), B = WtH.
#define BM 128
#define BK2 32              // halves per chunk (2 k-steps of 16)
#define SW 20               // 32-bit words per row per stage (16 used + 4 pad)
#define NCH2 48             // 1536 / 32

__global__ __launch_bounds__(256, 2) void k_gemm(const __half* __restrict__ WtH,
                                                 const float* __restrict__ bl) {
    __shared__ unsigned sA[2][BM * SW];
    __shared__ unsigned sB[2][DD * SW];
    __shared__ float sBias[DD];
    __shared__ float sSum[DD], sSq[DD];

    int bm = blockIdx.x * BM;
    int tid = threadIdx.x;
    int lane = tid & 31;
    int warp = tid >> 5;
    int g = lane >> 2;
    int t = lane & 3;
    int m_base = (warp >> 2) * 64;
    int n_base = (warp & 3) * 32;

    if (tid < DD) {
        sBias[tid] = bl[tid];
        sSum[tid] = 0.f;
        sSq[tid] = 0.f;
    }
    __syncthreads();

    float acc[4][4][4];
#pragma unroll
    for (int i = 0; i < 4; i++)
#pragma unroll
        for (int j = 0; j < 4; j++)
#pragma unroll
            for (int c = 0; c < 4; c++) acc[i][j][c] = 0.f;

    // cp.async staging: idx = tid + u*256 (u<2): row = idx>>2 (0..127), seg = idx&3 (16B)
    const int cpRow = tid >> 2;
    const int cpSeg = tid & 3;
    const int row2 = cpRow + 64;              // second row for u=1 (idx>>2 = 64 + tid>>2)

    // smem byte bases
    const unsigned aTile = (unsigned)__cvta_generic_to_shared(&sA[0][0]);
    const unsigned bTile = (unsigned)__cvta_generic_to_shared(&sB[0][0]);
    const unsigned stageBytes = BM * SW * 4;

    auto cpAB = [&](int chunk, int buf) {
        unsigned aD = aTile + buf * stageBytes;
        unsigned bD = bTile + buf * stageBytes;
#pragma unroll
        for (int u = 0; u < 2; u++) {
            int row = u ? row2 : cpRow;
            unsigned dst = (unsigned)(row * SW + cpSeg * 4) * 4u;
            const unsigned* pa = g_aggsH + (size_t)(bm + row) * 768 + chunk * 16 + cpSeg * 4;
            cp_async16p(aD + dst, pa, (bm + row) < NN ? 16 : 0);
            cp_async16(bD + dst, WtH + (size_t)row * 1536 + chunk * BK2 + cpSeg * 8);
        }
    };

    // ldmatrix lane offsets (bytes within tile)
    const int l8 = lane & 7;
    const unsigned aLane = (unsigned)((l8 + ((lane >> 3) & 1) * 8) * SW * 4 + ((lane >> 4) & 1) * 16);
    const unsigned bLane = (unsigned)((l8 + ((lane >> 4) & 1) * 8) * SW * 4 + ((lane >> 3) & 1) * 16);

    auto mmaChunk = [&](int buf) {
        unsigned aBase = aTile + buf * stageBytes + (unsigned)(m_base * SW * 4) + aLane;
        unsigned bBase = bTile + buf * stageBytes + (unsigned)(n_base * SW * 4) + bLane;
#pragma unroll
        for (int ks = 0; ks < 2; ks++) {
            unsigned bf[4][2];
            ldsm_x4(bf[0][0], bf[0][1], bf[1][0], bf[1][1], bBase + ks * 32);
            ldsm_x4(bf[2][0], bf[2][1], bf[3][0], bf[3][1], bBase + 16 * SW * 4 + ks * 32);
#pragma unroll
            for (int i = 0; i < 4; i++) {
                unsigned a0, a1, a2, a3;
                ldsm_x4(a0, a1, a2, a3, aBase + (unsigned)(i * 16 * SW * 4) + ks * 32);
#pragma unroll
                for (int j = 0; j < 4; j++) {
                    asm volatile(
                        "mma.sync.aligned.m16n8k16.row.col.f32.f16.f16.f32 "
                        "{%0,%1,%2,%3}, {%4,%5,%6,%7}, {%8,%9}, {%0,%1,%2,%3};"
                        : "+f"(acc[i][j][0]), "+f"(acc[i][j][1]),
                          "+f"(acc[i][j][2]), "+f"(acc[i][j][3])
                        : "r"(a0), "r"(a1), "r"(a2), "r"(a3),
                          "r"(bf[j][0]), "r"(bf[j][1]));
                }
            }
        }
    };

    cpAB(0, 0);
    cp_commit();

    for (int c = 0; c < NCH2; c++) {
        cp_wait0();
        __syncthreads();
        if (c + 1 < NCH2) {
            cpAB(c + 1, (c + 1) & 1);
            cp_commit();
        }
        mmaChunk(c & 1);
    }

    // epilogue: bias + store
#pragma unroll
    for (int i = 0; i < 4; i++) {
        int r0 = bm + m_base + i * 16 + g;
        int r1 = r0 + 8;
#pragma unroll
        for (int j = 0; j < 4; j++) {
            int col = n_base + j * 8 + t * 2;
            float bx = sBias[col], by = sBias[col + 1];
            acc[i][j][0] += bx; acc[i][j][1] += by;
            acc[i][j][2] += bx; acc[i][j][3] += by;
            if (r0 < NN)
                *(float2*)&g_out[(size_t)r0 * DD + col] = make_float2(acc[i][j][0], acc[i][j][1]);
            if (r1 < NN)
                *(float2*)&g_out[(size_t)r1 * DD + col] = make_float2(acc[i][j][2], acc[i][j][3]);
        }
    }

    // fused BN stats: per-column sum/sumsq over valid rows
#pragma unroll
    for (int j = 0; j < 4; j++)
#pragma unroll
        for (int c2 = 0; c2 < 2; c2++) {
            int col = n_base + j * 8 + t * 2 + c2;
            float s = 0.f, q = 0.f;
#pragma unroll
            for (int i = 0; i < 4; i++) {
                int r0 = bm + m_base + i * 16 + g;
                float v0 = acc[i][j][c2];
                float v1 = acc[i][j][2 + c2];
                if (r0 < NN) { s += v0; q += v0 * v0; }
                if (r0 + 8 < NN) { s += v1; q += v1 * v1; }
            }
#pragma unroll
            for (int m = 4; m <= 16; m <<= 1) {
                s += __shfl_xor_sync(0xffffffffu, s, m);
                q += __shfl_xor_sync(0xffffffffu, q, m);
            }
            if (g == 0) {
                atomicAdd(&sSum[col], s);
                atomicAdd(&sSq[col], q);
            }
        }
    __syncthreads();
    if (tid < DD) {
        atomicAdd(&g_bnsum[tid], sSum[tid]);
        atomicAdd(&g_bnsq[tid], sSq[tid]);
    }
}

// BN apply with inline param computation + residual + fp16 mirror
__global__ void k_bnapply(const float* __restrict__ gamma, const float* __restrict__ beta) {
    int t = blockIdx.x * blockDim.x + threadIdx.x;
    if (t >= NN * 32) return;
    int c = (t & 31) * 4;
    float mu[4], rsg[4], bt[4];
#pragma unroll
    for (int u = 0; u < 4; u++) {
        float m = g_bnsum[c + u] / (float)NN;
        float var = g_bnsq[c + u] / (float)NN - m * m;
        mu[u] = m;
        rsg[u] = rsqrtf(var + EPSF) * gamma[c + u];
        bt[u] = beta[c + u];
    }
    float4 o = ((const float4*)g_out)[t];
    float4 h = ((float4*)g_h)[t];
    o.x = fmaxf((o.x - mu[0]) * rsg[0] + bt[0], 0.f) + h.x;
    o.y = fmaxf((o.y - mu[1]) * rsg[1] + bt[1], 0.f) + h.y;
    o.z = fmaxf((o.z - mu[2]) * rsg[2] + bt[2], 0.f) + h.z;
    o.w = fmaxf((o.w - mu[3]) * rsg[3] + bt[3], 0.f) + h.w;
    ((float4*)g_h)[t] = o;
    ((uint2*)g_hH)[t] = make_uint2(packh2(o.x, o.y), packh2(o.z, o.w));
}

// ---------------- fused pooling + MLP: one block per graph ----------------
__global__ void k_poolmlp(const float* __restrict__ W1, const float* __restrict__ b1,
                          const float* __restrict__ W2, const float* __restrict__ b2,
                          const float* __restrict__ W3, const float* __restrict__ b3,
                          float* __restrict__ out) {
    __shared__ float sg[DD], sz1[64], sz2[32];
    int gid = blockIdx.x;
    int tid = threadIdx.x;      // 128 threads, one per feature
    int beg = g_goff[gid], end = g_goff[gid + 1];
    float s = 0.f;
    for (int r = beg; r < end; r++) s += g_h[(size_t)r * DD + tid];
    sg[tid] = s / (float)max(end - beg, 1);
    __syncthreads();
    if (tid < 64) {
        float a = b1[tid];
        for (int k = 0; k < DD; k++) a += sg[k] * W1[k * 64 + tid];
        sz1[tid] = fmaxf(a, 0.f);
    }
    __syncthreads();
    if (tid < 32) {
        float a = b2[tid];
        for (int k = 0; k < 64; k++) a += sz1[k] * W2[k * 32 + tid];
        sz2[tid] = fmaxf(a, 0.f);
    }
    __syncthreads();
    if (tid < NT) {
        float a = b3[tid];
        for (int k = 0; k < 32; k++) a += sz2[k] * W3[k * NT + tid];
        out[gid * NT + tid] = a;
    }
}

// ---------------- launch ----------------
extern "C" void kernel_launch(void* const* d_in, const int* in_sizes, int n_in,
                              void* d_out, int out_size) {
    const float* x      = (const float*)d_in[0];
    const int*   ei     = (const int*)d_in[1];
    const int*   batch  = (const int*)d_in[2];
    const float* emb_W  = (const float*)d_in[3];
    const float* emb_b  = (const float*)d_in[4];
    const float* conv_W = (const float*)d_in[5];
    const float* conv_b = (const float*)d_in[6];
    const float* bng    = (const float*)d_in[7];
    const float* bnb    = (const float*)d_in[8];
    const float* W1     = (const float*)d_in[9];
    const float* b1     = (const float*)d_in[10];
    const float* W2     = (const float*)d_in[11];
    const float* b2     = (const float*)d_in[12];
    const float* W3     = (const float*)d_in[13];
    const float* b3     = (const float*)d_in[14];
    float* out = (float*)d_out;

    k_zero<<<(NN + 255) / 256, 256>>>();
    k_hist<<<(NE + 255) / 256, 256>>>(ei, batch);
    k_scan<<<1, 1024>>>();
    k_delta<<<(NN + 255) / 256, 256>>>();
    k_scalars<<<(NN + 255) / 256, 256>>>();
    k_scatter<<<(NE + 255) / 256, 256>>>(ei);
    k_emb<<<(NN * 32 + 255) / 256, 256>>>(x, emb_W, emb_b);
    k_wprep<<<(NL * 1536 * DD + 255) / 256, 256>>>(conv_W);

    __half* g_WtH_ptr;
    cudaGetSymbolAddress((void**)&g_WtH_ptr, g_WtH);

    for (int l = 0; l < NL; l++) {
        k_agg<<<(NN * 32 + 255) / 256, 256>>>();
        k_gemm<<<(NN + BM - 1) / BM, 256>>>(g_WtH_ptr + (size_t)l * DD * 1536,
                                            conv_b + (size_t)l * DD);
        k_bnapply<<<(NN * 32 + 255) / 256, 256>>>(bng + (size_t)l * DD, bnb + (size_t)l * DD);
    }

    k_poolmlp<<<NG, DD>>>(W1, b1, W2, b2, W3, b3, out);
}

// round 13
// speedup vs baseline: 1.9902x; 1.1490x over previous
#include <cuda_runtime.h>
#include <cuda_fp16.h>
#include <math.h>

#define NN 50000
#define NE 600000
#define DD 128
#define NL 4
#define NG 512
#define NT 10
#define EPSF 1e-5f

// ---------------- scratch (static device allocations) ----------------
__device__ int   g_deg[NN];
__device__ int   g_rowptr[NN + 1];
__device__ int   g_cursor[NN];
__device__ int   g_srcperm[NE];
__device__ float g_amp[NN], g_att[NN], g_dinv[NN];
__device__ float g_delta_acc;
__device__ float g_h[NN * DD];
__device__ unsigned g_hH[NN * DD / 2];              // fp16 mirror of g_h (packed half2)
__device__ unsigned g_aggsH[(size_t)NN * 768];      // [N][1536] halves: [aggs|amp*aggs|att*aggs]
__device__ float g_out[NN * DD];
__device__ float g_bnsum[DD], g_bnsq[DD];
__device__ int   g_gcnt[NG];
__device__ int   g_goff[NG + 1];
__device__ __half g_WtH[(size_t)NL * DD * 1536];    // W transposed fp16: [l][n][k]

// ---------------- small helpers ----------------
__device__ __forceinline__ float4 f4zero() { return make_float4(0.f, 0.f, 0.f, 0.f); }

__device__ __forceinline__ unsigned packh2(float a, float b) {
    __half2 h = __floats2half2_rn(a, b);
    return *(unsigned*)&h;
}

__device__ __forceinline__ void cp_async16(unsigned smem_addr, const void* gptr) {
    asm volatile("cp.async.cg.shared.global [%0], [%1], 16;" :: "r"(smem_addr), "l"(gptr));
}
__device__ __forceinline__ void cp_async16p(unsigned smem_addr, const void* gptr, int szbytes) {
    asm volatile("cp.async.cg.shared.global [%0], [%1], 16, %2;"
                 :: "r"(smem_addr), "l"(gptr), "r"(szbytes));
}
__device__ __forceinline__ void cp_commit() { asm volatile("cp.async.commit_group;"); }
__device__ __forceinline__ void cp_wait0() { asm volatile("cp.async.wait_group 0;"); }
__device__ __forceinline__ void cp_wait1() { asm volatile("cp.async.wait_group 1;"); }

__device__ __forceinline__ void ldsm_x4(unsigned& r0, unsigned& r1, unsigned& r2, unsigned& r3,
                                        unsigned addr) {
    asm volatile("ldmatrix.sync.aligned.m8n8.x4.shared.b16 {%0,%1,%2,%3}, [%4];"
                 : "=r"(r0), "=r"(r1), "=r"(r2), "=r"(r3) : "r"(addr));
}

// ---------------- setup kernels ----------------
__global__ void k_zero() {
    int i = blockIdx.x * blockDim.x + threadIdx.x;
    if (i < NN) { g_deg[i] = 0; g_cursor[i] = 0; }
    if (i < NG) g_gcnt[i] = 0;
    if (i == 0) g_delta_acc = 0.f;
}

__global__ void k_hist(const int* __restrict__ ei, const int* __restrict__ batch) {
    int e = blockIdx.x * blockDim.x + threadIdx.x;
    if (e < NE) atomicAdd(&g_deg[ei[NE + e]], 1);     // dst row
    if (e < NN) atomicAdd(&g_gcnt[batch[e]], 1);
}

__global__ void k_scan() {
    __shared__ int s[1024];
    int t = threadIdx.x;
    const int C = (NN + 1023) / 1024;
    int base = t * C;
    int acc = 0;
    for (int c = 0; c < C; c++) { int i = base + c; if (i < NN) acc += g_deg[i]; }
    s[t] = acc;
    __syncthreads();
    for (int d = 1; d < 1024; d <<= 1) {
        int add = (t >= d) ? s[t - d] : 0;
        __syncthreads();
        s[t] += add;
        __syncthreads();
    }
    int off = s[t] - acc;
    for (int c = 0; c < C; c++) { int i = base + c; if (i < NN) { g_rowptr[i] = off; off += g_deg[i]; } }
    if (t == 0) g_rowptr[NN] = NE;
    __syncthreads();
    int v = (t < NG) ? g_gcnt[t] : 0;
    s[t] = v;
    __syncthreads();
    for (int d = 1; d < 1024; d <<= 1) {
        int add = (t >= d) ? s[t - d] : 0;
        __syncthreads();
        s[t] += add;
        __syncthreads();
    }
    if (t < NG) g_goff[t] = s[t] - v;
    if (t == 0) g_goff[NG] = NN;
}

__global__ void k_delta() {
    int i = blockIdx.x * blockDim.x + threadIdx.x;
    float v = (i < NN) ? log1pf((float)g_deg[i]) : 0.f;
    for (int o = 16; o; o >>= 1) v += __shfl_down_sync(0xffffffffu, v, o);
    __shared__ float ws[8];
    if ((threadIdx.x & 31) == 0) ws[threadIdx.x >> 5] = v;
    __syncthreads();
    if (threadIdx.x < 8) {
        v = ws[threadIdx.x];
        for (int o = 4; o; o >>= 1) v += __shfl_down_sync(0xffu, v, o);
        if (threadIdx.x == 0) atomicAdd(&g_delta_acc, v);
    }
}

__global__ void k_scalars() {
    int i = blockIdx.x * blockDim.x + threadIdx.x;
    if (i >= NN) return;
    float deg = (float)g_deg[i];
    float d = fmaxf(deg, 1.f);
    float ld = log1pf(d);
    float delta = g_delta_acc / (float)NN;
    g_amp[i] = ld / delta;
    g_att[i] = delta / ld;
    g_dinv[i] = 1.f / d;
}

__global__ void k_scatter(const int* __restrict__ ei) {
    int e = blockIdx.x * blockDim.x + threadIdx.x;
    if (e >= NE) return;
    int dst = ei[NE + e];
    int p = atomicAdd(&g_cursor[dst], 1);
    g_srcperm[g_rowptr[dst] + p] = ei[e];
}

__global__ void k_emb(const float* __restrict__ x, const float* __restrict__ W,
                      const float* __restrict__ b) {
    int t = blockIdx.x * blockDim.x + threadIdx.x;
    int i = t >> 5, c = t & 31;
    if (i >= NN) return;
    float x0 = x[i * 3 + 0], x1 = x[i * 3 + 1], x2 = x[i * 3 + 2];
    float4 w0 = *(const float4*)&W[0 * DD + c * 4];
    float4 w1 = *(const float4*)&W[1 * DD + c * 4];
    float4 w2 = *(const float4*)&W[2 * DD + c * 4];
    float4 bb = *(const float4*)&b[c * 4];
    float4 h;
    h.x = bb.x + x0 * w0.x + x1 * w1.x + x2 * w2.x;
    h.y = bb.y + x0 * w0.y + x1 * w1.y + x2 * w2.y;
    h.z = bb.z + x0 * w0.z + x1 * w1.z + x2 * w2.z;
    h.w = bb.w + x0 * w0.w + x1 * w1.w + x2 * w2.w;
    ((float4*)g_h)[i * 32 + c] = h;
    ((uint2*)g_hH)[i * 32 + c] = make_uint2(packh2(h.x, h.y), packh2(h.z, h.w));
}

// Transpose + fp16-convert conv weights: g_WtH[l][n][k] = half(W[l][k][n])
__global__ void k_wprep(const float* __restrict__ conv_W) {
    int t = blockIdx.x * blockDim.x + threadIdx.x;
    if (t >= NL * 1536 * DD) return;
    int l = t / (1536 * DD);
    int r = t - l * (1536 * DD);
    int k = r >> 7;           // 0..1535
    int n = r & 127;          // coalesced read along n
    g_WtH[((size_t)l * DD + n) * 1536 + k] = __float2half_rn(conv_W[t]);
}

// ---------------- per-layer kernels ----------------
// warp per node; gathers fp16 h rows; writes pre-scaled fp16 A matrix (3 slabs).
__global__ void k_agg() {
    if (blockIdx.x == 0 && threadIdx.x < DD) {    // reset BN accumulators for this layer
        g_bnsum[threadIdx.x] = 0.f;
        g_bnsq[threadIdx.x] = 0.f;
    }
    int warp = (blockIdx.x * blockDim.x + threadIdx.x) >> 5;
    int lane = threadIdx.x & 31;
    if (warp >= NN) return;
    int beg = g_rowptr[warp], end = g_rowptr[warp + 1];
    float4 s1 = f4zero(), s2 = f4zero();
    float4 mn = make_float4(INFINITY, INFINITY, INFINITY, INFINITY);
    float4 mx = make_float4(-INFINITY, -INFINITY, -INFINITY, -INFINITY);
    const uint2* hp = (const uint2*)g_hH;
    for (int e = beg; e < end; e += 32) {
        int myj = (e + lane < end) ? g_srcperm[e + lane] : 0;
        int cnt = min(32, end - e);
#pragma unroll 8
        for (int kk = 0; kk < cnt; kk++) {
            int j = __shfl_sync(0xffffffffu, myj, kk);
            uint2 v = hp[j * 32 + lane];
            float2 f01 = __half22float2(*(__half2*)&v.x);
            float2 f23 = __half22float2(*(__half2*)&v.y);
            float4 m = make_float4(f01.x, f01.y, f23.x, f23.y);
            s1.x += m.x; s1.y += m.y; s1.z += m.z; s1.w += m.w;
            s2.x += m.x * m.x; s2.y += m.y * m.y; s2.z += m.z * m.z; s2.w += m.w * m.w;
            mn.x = fminf(mn.x, m.x); mn.y = fminf(mn.y, m.y); mn.z = fminf(mn.z, m.z); mn.w = fminf(mn.w, m.w);
            mx.x = fmaxf(mx.x, m.x); mx.y = fmaxf(mx.y, m.y); mx.z = fmaxf(mx.z, m.z); mx.w = fmaxf(mx.w, m.w);
        }
    }
    float dinv = g_dinv[warp];
    float4 mean, sd;
    mean.x = s1.x * dinv; mean.y = s1.y * dinv; mean.z = s1.z * dinv; mean.w = s1.w * dinv;
    sd.x = sqrtf(fmaxf(s2.x * dinv - mean.x * mean.x, 0.f) + EPSF);
    sd.y = sqrtf(fmaxf(s2.y * dinv - mean.y * mean.y, 0.f) + EPSF);
    sd.z = sqrtf(fmaxf(s2.z * dinv - mean.z * mean.z, 0.f) + EPSF);
    sd.w = sqrtf(fmaxf(s2.w * dinv - mean.w * mean.w, 0.f) + EPSF);
    if (beg == end) { mn = f4zero(); mx = f4zero(); }

    float amp = g_amp[warp], att = g_att[warp];
    float4 ag[4] = { mean, mn, mx, sd };
    unsigned* base = g_aggsH + (size_t)warp * 768;   // uints; 256 per slab
#pragma unroll
    for (int s = 0; s < 3; s++) {
        float sc = (s == 0) ? 1.f : ((s == 1) ? amp : att);
#pragma unroll
        for (int a = 0; a < 4; a++) {
            uint2 w;
            w.x = packh2(ag[a].x * sc, ag[a].y * sc);
            w.y = packh2(ag[a].z * sc, ag[a].w * sc);
            *(uint2*)&base[s * 256 + a * 64 + lane * 2] = w;
        }
    }
}

// ---------------- FP16 tensor-core GEMM (m16n8k16), ldmatrix + BK=32, 3-stage ----------------
// C[128 x 128] per block; 8 warps each 64x32. A = g_aggsH (pre-scaled fp16), B = WtH.
#define BM 128
#define BK2 32              // halves per chunk (2 k-steps of 16)
#define SW 20               // 32-bit words per row per stage (16 used + 4 pad)
#define NCH2 48             // 1536 / 32
#define GSTAGES 3
#define STAGE_BYTES (BM * SW * 4)            // 10240 per tile
#define GM_DYN (2 * GSTAGES * STAGE_BYTES)   // 61440

__global__ __launch_bounds__(256, 2) void k_gemm(const __half* __restrict__ WtH,
                                                 const float* __restrict__ bl) {
    extern __shared__ unsigned dynS[];
    __shared__ float sBias[DD];
    __shared__ float sSum[DD], sSq[DD];

    int bm = blockIdx.x * BM;
    int tid = threadIdx.x;
    int lane = tid & 31;
    int warp = tid >> 5;
    int g = lane >> 2;
    int t = lane & 3;
    int m_base = (warp >> 2) * 64;
    int n_base = (warp & 3) * 32;

    if (tid < DD) {
        sBias[tid] = bl[tid];
        sSum[tid] = 0.f;
        sSq[tid] = 0.f;
    }
    __syncthreads();

    float acc[4][4][4];
#pragma unroll
    for (int i = 0; i < 4; i++)
#pragma unroll
        for (int j = 0; j < 4; j++)
#pragma unroll
            for (int c = 0; c < 4; c++) acc[i][j][c] = 0.f;

    // cp.async staging: idx = tid + u*256 (u<2): row = idx>>2 (0..127), seg = idx&3 (16B)
    const int cpRow = tid >> 2;
    const int cpSeg = tid & 3;
    const int row2 = cpRow + 64;

    // smem byte bases (dynamic): A stages [0,3), then B stages
    const unsigned aTile = (unsigned)__cvta_generic_to_shared(&dynS[0]);
    const unsigned bTile = aTile + GSTAGES * STAGE_BYTES;

    auto cpAB = [&](int chunk, int buf) {
        unsigned aD = aTile + buf * STAGE_BYTES;
        unsigned bD = bTile + buf * STAGE_BYTES;
#pragma unroll
        for (int u = 0; u < 2; u++) {
            int row = u ? row2 : cpRow;
            unsigned dst = (unsigned)(row * SW + cpSeg * 4) * 4u;
            const unsigned* pa = g_aggsH + (size_t)(bm + row) * 768 + chunk * 16 + cpSeg * 4;
            cp_async16p(aD + dst, pa, (bm + row) < NN ? 16 : 0);
            cp_async16(bD + dst, WtH + (size_t)row * 1536 + chunk * BK2 + cpSeg * 8);
        }
    };

    // ldmatrix lane offsets (bytes within tile)
    const int l8 = lane & 7;
    const unsigned aLane = (unsigned)((l8 + ((lane >> 3) & 1) * 8) * SW * 4 + ((lane >> 4) & 1) * 16);
    const unsigned bLane = (unsigned)((l8 + ((lane >> 4) & 1) * 8) * SW * 4 + ((lane >> 3) & 1) * 16);

    auto mmaChunk = [&](int buf) {
        unsigned aBase = aTile + buf * STAGE_BYTES + (unsigned)(m_base * SW * 4) + aLane;
        unsigned bBase = bTile + buf * STAGE_BYTES + (unsigned)(n_base * SW * 4) + bLane;
#pragma unroll
        for (int ks = 0; ks < 2; ks++) {
            unsigned bf[4][2];
            ldsm_x4(bf[0][0], bf[0][1], bf[1][0], bf[1][1], bBase + ks * 32);
            ldsm_x4(bf[2][0], bf[2][1], bf[3][0], bf[3][1], bBase + 16 * SW * 4 + ks * 32);
#pragma unroll
            for (int i = 0; i < 4; i++) {
                unsigned a0, a1, a2, a3;
                ldsm_x4(a0, a1, a2, a3, aBase + (unsigned)(i * 16 * SW * 4) + ks * 32);
#pragma unroll
                for (int j = 0; j < 4; j++) {
                    asm volatile(
                        "mma.sync.aligned.m16n8k16.row.col.f32.f16.f16.f32 "
                        "{%0,%1,%2,%3}, {%4,%5,%6,%7}, {%8,%9}, {%0,%1,%2,%3};"
                        : "+f"(acc[i][j][0]), "+f"(acc[i][j][1]),
                          "+f"(acc[i][j][2]), "+f"(acc[i][j][3])
                        : "r"(a0), "r"(a1), "r"(a2), "r"(a3),
                          "r"(bf[j][0]), "r"(bf[j][1]));
                }
            }
        }
    };

    // prologue: prefetch chunks 0 and 1
    cpAB(0, 0); cp_commit();
    cpAB(1, 1); cp_commit();

    for (int c = 0; c < NCH2; c++) {
        if (c + 1 < NCH2) cp_wait1(); else cp_wait0();
        __syncthreads();
        if (c + 2 < NCH2) {
            cpAB(c + 2, (c + 2) % GSTAGES);
            cp_commit();
        }
        mmaChunk(c % GSTAGES);
    }

    // epilogue: bias + store
#pragma unroll
    for (int i = 0; i < 4; i++) {
        int r0 = bm + m_base + i * 16 + g;
        int r1 = r0 + 8;
#pragma unroll
        for (int j = 0; j < 4; j++) {
            int col = n_base + j * 8 + t * 2;
            float bx = sBias[col], by = sBias[col + 1];
            acc[i][j][0] += bx; acc[i][j][1] += by;
            acc[i][j][2] += bx; acc[i][j][3] += by;
            if (r0 < NN)
                *(float2*)&g_out[(size_t)r0 * DD + col] = make_float2(acc[i][j][0], acc[i][j][1]);
            if (r1 < NN)
                *(float2*)&g_out[(size_t)r1 * DD + col] = make_float2(acc[i][j][2], acc[i][j][3]);
        }
    }

    // fused BN stats: per-column sum/sumsq over valid rows
#pragma unroll
    for (int j = 0; j < 4; j++)
#pragma unroll
        for (int c2 = 0; c2 < 2; c2++) {
            int col = n_base + j * 8 + t * 2 + c2;
            float s = 0.f, q = 0.f;
#pragma unroll
            for (int i = 0; i < 4; i++) {
                int r0 = bm + m_base + i * 16 + g;
                float v0 = acc[i][j][c2];
                float v1 = acc[i][j][2 + c2];
                if (r0 < NN) { s += v0; q += v0 * v0; }
                if (r0 + 8 < NN) { s += v1; q += v1 * v1; }
            }
#pragma unroll
            for (int m = 4; m <= 16; m <<= 1) {
                s += __shfl_xor_sync(0xffffffffu, s, m);
                q += __shfl_xor_sync(0xffffffffu, q, m);
            }
            if (g == 0) {
                atomicAdd(&sSum[col], s);
                atomicAdd(&sSq[col], q);
            }
        }
    __syncthreads();
    if (tid < DD) {
        atomicAdd(&g_bnsum[tid], sSum[tid]);
        atomicAdd(&g_bnsq[tid], sSq[tid]);
    }
}

// BN apply with inline param computation + residual + fp16 mirror
__global__ void k_bnapply(const float* __restrict__ gamma, const float* __restrict__ beta) {
    int t = blockIdx.x * blockDim.x + threadIdx.x;
    if (t >= NN * 32) return;
    int c = (t & 31) * 4;
    float mu[4], rsg[4], bt[4];
#pragma unroll
    for (int u = 0; u < 4; u++) {
        float m = g_bnsum[c + u] / (float)NN;
        float var = g_bnsq[c + u] / (float)NN - m * m;
        mu[u] = m;
        rsg[u] = rsqrtf(var + EPSF) * gamma[c + u];
        bt[u] = beta[c + u];
    }
    float4 o = ((const float4*)g_out)[t];
    float4 h = ((float4*)g_h)[t];
    o.x = fmaxf((o.x - mu[0]) * rsg[0] + bt[0], 0.f) + h.x;
    o.y = fmaxf((o.y - mu[1]) * rsg[1] + bt[1], 0.f) + h.y;
    o.z = fmaxf((o.z - mu[2]) * rsg[2] + bt[2], 0.f) + h.z;
    o.w = fmaxf((o.w - mu[3]) * rsg[3] + bt[3], 0.f) + h.w;
    ((float4*)g_h)[t] = o;
    ((uint2*)g_hH)[t] = make_uint2(packh2(o.x, o.y), packh2(o.z, o.w));
}

// ---------------- fused pooling + MLP: one block per graph ----------------
__global__ void k_poolmlp(const float* __restrict__ W1, const float* __restrict__ b1,
                          const float* __restrict__ W2, const float* __restrict__ b2,
                          const float* __restrict__ W3, const float* __restrict__ b3,
                          float* __restrict__ out) {
    __shared__ float sg[DD], sz1[64], sz2[32];
    int gid = blockIdx.x;
    int tid = threadIdx.x;      // 128 threads, one per feature
    int beg = g_goff[gid], end = g_goff[gid + 1];
    float s = 0.f;
    for (int r = beg; r < end; r++) s += g_h[(size_t)r * DD + tid];
    sg[tid] = s / (float)max(end - beg, 1);
    __syncthreads();
    if (tid < 64) {
        float a = b1[tid];
        for (int k = 0; k < DD; k++) a += sg[k] * W1[k * 64 + tid];
        sz1[tid] = fmaxf(a, 0.f);
    }
    __syncthreads();
    if (tid < 32) {
        float a = b2[tid];
        for (int k = 0; k < 64; k++) a += sz1[k] * W2[k * 32 + tid];
        sz2[tid] = fmaxf(a, 0.f);
    }
    __syncthreads();
    if (tid < NT) {
        float a = b3[tid];
        for (int k = 0; k < 32; k++) a += sz2[k] * W3[k * NT + tid];
        out[gid * NT + tid] = a;
    }
}

// ---------------- launch ----------------
extern "C" void kernel_launch(void* const* d_in, const int* in_sizes, int n_in,
                              void* d_out, int out_size) {
    const float* x      = (const float*)d_in[0];
    const int*   ei     = (const int*)d_in[1];
    const int*   batch  = (const int*)d_in[2];
    const float* emb_W  = (const float*)d_in[3];
    const float* emb_b  = (const float*)d_in[4];
    const float* conv_W = (const float*)d_in[5];
    const float* conv_b = (const float*)d_in[6];
    const float* bng    = (const float*)d_in[7];
    const float* bnb    = (const float*)d_in[8];
    const float* W1     = (const float*)d_in[9];
    const float* b1     = (const float*)d_in[10];
    const float* W2     = (const float*)d_in[11];
    const float* b2     = (const float*)d_in[12];
    const float* W3     = (const float*)d_in[13];
    const float* b3     = (const float*)d_in[14];
    float* out = (float*)d_out;

    cudaFuncSetAttribute(k_gemm, cudaFuncAttributeMaxDynamicSharedMemorySize, GM_DYN);

    k_zero<<<(NN + 255) / 256, 256>>>();
    k_hist<<<(NE + 255) / 256, 256>>>(ei, batch);
    k_scan<<<1, 1024>>>();
    k_delta<<<(NN + 255) / 256, 256>>>();
    k_scalars<<<(NN + 255) / 256, 256>>>();
    k_scatter<<<(NE + 255) / 256, 256>>>(ei);
    k_emb<<<(NN * 32 + 255) / 256, 256>>>(x, emb_W, emb_b);
    k_wprep<<<(NL * 1536 * DD + 255) / 256, 256>>>(conv_W);

    __half* g_WtH_ptr;
    cudaGetSymbolAddress((void**)&g_WtH_ptr, g_WtH);

    for (int l = 0; l < NL; l++) {
        k_agg<<<(NN * 32 + 255) / 256, 256>>>();
        k_gemm<<<(NN + BM - 1) / BM, 256, GM_DYN>>>(g_WtH_ptr + (size_t)l * DD * 1536,
                                                    conv_b + (size_t)l * DD);
        k_bnapply<<<(NN * 32 + 255) / 256, 256>>>(bng + (size_t)l * DD, bnb + (size_t)l * DD);
    }

    k_poolmlp<<<NG, DD>>>(W1, b1, W2, b2, W3, b3, out);
}

// round 14
// speedup vs baseline: 2.2040x; 1.1075x over previous
#include <cuda_runtime.h>
#include <cuda_fp16.h>
#include <math.h>

#define NN 50000
#define NE 600000
#define DD 128
#define NL 4
#define NG 512
#define NT 10
#define EPSF 1e-5f

// ---------------- scratch (static device allocations) ----------------
__device__ int   g_deg[NN];
__device__ int   g_rowptr[NN + 1];
__device__ int   g_cursor[NN];
__device__ int   g_srcperm[NE];
__device__ float g_amp[NN], g_att[NN], g_dinv[NN];
__device__ float g_delta_acc;
__device__ float g_h[NN * DD];
__device__ unsigned g_hH[NN * DD / 2];              // fp16 mirror of g_h (packed half2)
__device__ unsigned g_aggsH[(size_t)NN * 256];      // [N][512] halves: unscaled mean|min|max|std
__device__ float g_out[NN * DD];
__device__ float g_bnsum[DD], g_bnsq[DD];
__device__ int   g_gcnt[NG];
__device__ int   g_goff[NG + 1];
__device__ __half g_WtH[(size_t)NL * DD * 1536];    // W transposed fp16: [l][n][k]

// ---------------- small helpers ----------------
__device__ __forceinline__ float4 f4zero() { return make_float4(0.f, 0.f, 0.f, 0.f); }

__device__ __forceinline__ unsigned packh2(float a, float b) {
    __half2 h = __floats2half2_rn(a, b);
    return *(unsigned*)&h;
}
__device__ __forceinline__ unsigned hmul2u(unsigned a, unsigned s) {
    __half2 r = __hmul2(*(__half2*)&a, *(__half2*)&s);
    return *(unsigned*)&r;
}

__device__ __forceinline__ void cp_async16(unsigned smem_addr, const void* gptr) {
    asm volatile("cp.async.cg.shared.global [%0], [%1], 16;" :: "r"(smem_addr), "l"(gptr));
}
__device__ __forceinline__ void cp_async16p(unsigned smem_addr, const void* gptr, int szbytes) {
    asm volatile("cp.async.cg.shared.global [%0], [%1], 16, %2;"
                 :: "r"(smem_addr), "l"(gptr), "r"(szbytes));
}
__device__ __forceinline__ void cp_commit() { asm volatile("cp.async.commit_group;"); }
__device__ __forceinline__ void cp_wait0() { asm volatile("cp.async.wait_group 0;"); }

__device__ __forceinline__ void ldsm_x4(unsigned& r0, unsigned& r1, unsigned& r2, unsigned& r3,
                                        unsigned addr) {
    asm volatile("ldmatrix.sync.aligned.m8n8.x4.shared.b16 {%0,%1,%2,%3}, [%4];"
                 : "=r"(r0), "=r"(r1), "=r"(r2), "=r"(r3) : "r"(addr));
}

#define MMA16816(acc, a0, a1, a2, a3, b0, b1) \
    asm volatile( \
        "mma.sync.aligned.m16n8k16.row.col.f32.f16.f16.f32 " \
        "{%0,%1,%2,%3}, {%4,%5,%6,%7}, {%8,%9}, {%0,%1,%2,%3};" \
        : "+f"((acc)[0]), "+f"((acc)[1]), "+f"((acc)[2]), "+f"((acc)[3]) \
        : "r"(a0), "r"(a1), "r"(a2), "r"(a3), "r"(b0), "r"(b1))

// ---------------- setup kernels ----------------
__global__ void k_zero() {
    int i = blockIdx.x * blockDim.x + threadIdx.x;
    if (i < NN) { g_deg[i] = 0; g_cursor[i] = 0; }
    if (i < NG) g_gcnt[i] = 0;
    if (i == 0) g_delta_acc = 0.f;
}

__global__ void k_hist(const int* __restrict__ ei, const int* __restrict__ batch) {
    int e = blockIdx.x * blockDim.x + threadIdx.x;
    if (e < NE) atomicAdd(&g_deg[ei[NE + e]], 1);     // dst row
    if (e < NN) atomicAdd(&g_gcnt[batch[e]], 1);
}

__global__ void k_scan() {
    __shared__ int s[1024];
    int t = threadIdx.x;
    const int C = (NN + 1023) / 1024;
    int base = t * C;
    int acc = 0;
    for (int c = 0; c < C; c++) { int i = base + c; if (i < NN) acc += g_deg[i]; }
    s[t] = acc;
    __syncthreads();
    for (int d = 1; d < 1024; d <<= 1) {
        int add = (t >= d) ? s[t - d] : 0;
        __syncthreads();
        s[t] += add;
        __syncthreads();
    }
    int off = s[t] - acc;
    for (int c = 0; c < C; c++) { int i = base + c; if (i < NN) { g_rowptr[i] = off; off += g_deg[i]; } }
    if (t == 0) g_rowptr[NN] = NE;
    __syncthreads();
    int v = (t < NG) ? g_gcnt[t] : 0;
    s[t] = v;
    __syncthreads();
    for (int d = 1; d < 1024; d <<= 1) {
        int add = (t >= d) ? s[t - d] : 0;
        __syncthreads();
        s[t] += add;
        __syncthreads();
    }
    if (t < NG) g_goff[t] = s[t] - v;
    if (t == 0) g_goff[NG] = NN;
}

__global__ void k_delta() {
    int i = blockIdx.x * blockDim.x + threadIdx.x;
    float v = (i < NN) ? log1pf((float)g_deg[i]) : 0.f;
    for (int o = 16; o; o >>= 1) v += __shfl_down_sync(0xffffffffu, v, o);
    __shared__ float ws[8];
    if ((threadIdx.x & 31) == 0) ws[threadIdx.x >> 5] = v;
    __syncthreads();
    if (threadIdx.x < 8) {
        v = ws[threadIdx.x];
        for (int o = 4; o; o >>= 1) v += __shfl_down_sync(0xffu, v, o);
        if (threadIdx.x == 0) atomicAdd(&g_delta_acc, v);
    }
}

__global__ void k_scalars() {
    int i = blockIdx.x * blockDim.x + threadIdx.x;
    if (i >= NN) return;
    float deg = (float)g_deg[i];
    float d = fmaxf(deg, 1.f);
    float ld = log1pf(d);
    float delta = g_delta_acc / (float)NN;
    g_amp[i] = ld / delta;
    g_att[i] = delta / ld;
    g_dinv[i] = 1.f / d;
}

__global__ void k_scatter(const int* __restrict__ ei) {
    int e = blockIdx.x * blockDim.x + threadIdx.x;
    if (e >= NE) return;
    int dst = ei[NE + e];
    int p = atomicAdd(&g_cursor[dst], 1);
    g_srcperm[g_rowptr[dst] + p] = ei[e];
}

__global__ void k_emb(const float* __restrict__ x, const float* __restrict__ W,
                      const float* __restrict__ b) {
    int t = blockIdx.x * blockDim.x + threadIdx.x;
    int i = t >> 5, c = t & 31;
    if (i >= NN) return;
    float x0 = x[i * 3 + 0], x1 = x[i * 3 + 1], x2 = x[i * 3 + 2];
    float4 w0 = *(const float4*)&W[0 * DD + c * 4];
    float4 w1 = *(const float4*)&W[1 * DD + c * 4];
    float4 w2 = *(const float4*)&W[2 * DD + c * 4];
    float4 bb = *(const float4*)&b[c * 4];
    float4 h;
    h.x = bb.x + x0 * w0.x + x1 * w1.x + x2 * w2.x;
    h.y = bb.y + x0 * w0.y + x1 * w1.y + x2 * w2.y;
    h.z = bb.z + x0 * w0.z + x1 * w1.z + x2 * w2.z;
    h.w = bb.w + x0 * w0.w + x1 * w1.w + x2 * w2.w;
    ((float4*)g_h)[i * 32 + c] = h;
    ((uint2*)g_hH)[i * 32 + c] = make_uint2(packh2(h.x, h.y), packh2(h.z, h.w));
}

// Transpose + fp16-convert conv weights: g_WtH[l][n][k] = half(W[l][k][n])
__global__ void k_wprep(const float* __restrict__ conv_W) {
    int t = blockIdx.x * blockDim.x + threadIdx.x;
    if (t >= NL * 1536 * DD) return;
    int l = t / (1536 * DD);
    int r = t - l * (1536 * DD);
    int k = r >> 7;           // 0..1535
    int n = r & 127;          // coalesced read along n
    g_WtH[((size_t)l * DD + n) * 1536 + k] = __float2half_rn(conv_W[t]);
}

// ---------------- per-layer kernels ----------------
// warp per node; gathers fp16 h rows; writes UNSCALED fp16 aggs [N][512].
__global__ void k_agg() {
    if (blockIdx.x == 0 && threadIdx.x < DD) {    // reset BN accumulators for this layer
        g_bnsum[threadIdx.x] = 0.f;
        g_bnsq[threadIdx.x] = 0.f;
    }
    int warp = (blockIdx.x * blockDim.x + threadIdx.x) >> 5;
    int lane = threadIdx.x & 31;
    if (warp >= NN) return;
    int beg = g_rowptr[warp], end = g_rowptr[warp + 1];
    float4 s1 = f4zero(), s2 = f4zero();
    float4 mn = make_float4(INFINITY, INFINITY, INFINITY, INFINITY);
    float4 mx = make_float4(-INFINITY, -INFINITY, -INFINITY, -INFINITY);
    const uint2* hp = (const uint2*)g_hH;
    for (int e = beg; e < end; e += 32) {
        int myj = (e + lane < end) ? g_srcperm[e + lane] : 0;
        int cnt = min(32, end - e);
#pragma unroll 8
        for (int kk = 0; kk < cnt; kk++) {
            int j = __shfl_sync(0xffffffffu, myj, kk);
            uint2 v = hp[j * 32 + lane];
            float2 f01 = __half22float2(*(__half2*)&v.x);
            float2 f23 = __half22float2(*(__half2*)&v.y);
            float4 m = make_float4(f01.x, f01.y, f23.x, f23.y);
            s1.x += m.x; s1.y += m.y; s1.z += m.z; s1.w += m.w;
            s2.x += m.x * m.x; s2.y += m.y * m.y; s2.z += m.z * m.z; s2.w += m.w * m.w;
            mn.x = fminf(mn.x, m.x); mn.y = fminf(mn.y, m.y); mn.z = fminf(mn.z, m.z); mn.w = fminf(mn.w, m.w);
            mx.x = fmaxf(mx.x, m.x); mx.y = fmaxf(mx.y, m.y); mx.z = fmaxf(mx.z, m.z); mx.w = fmaxf(mx.w, m.w);
        }
    }
    float dinv = g_dinv[warp];
    float4 mean, sd;
    mean.x = s1.x * dinv; mean.y = s1.y * dinv; mean.z = s1.z * dinv; mean.w = s1.w * dinv;
    sd.x = sqrtf(fmaxf(s2.x * dinv - mean.x * mean.x, 0.f) + EPSF);
    sd.y = sqrtf(fmaxf(s2.y * dinv - mean.y * mean.y, 0.f) + EPSF);
    sd.z = sqrtf(fmaxf(s2.z * dinv - mean.z * mean.z, 0.f) + EPSF);
    sd.w = sqrtf(fmaxf(s2.w * dinv - mean.w * mean.w, 0.f) + EPSF);
    if (beg == end) { mn = f4zero(); mx = f4zero(); }

    float4 ag[4] = { mean, mn, mx, sd };
    unsigned* base = g_aggsH + (size_t)warp * 256;
#pragma unroll
    for (int a = 0; a < 4; a++) {
        uint2 w;
        w.x = packh2(ag[a].x, ag[a].y);
        w.y = packh2(ag[a].z, ag[a].w);
        *(uint2*)&base[a * 64 + lane * 2] = w;
    }
}

// ---------------- FP16 tensor-core GEMM with in-fragment slab scaling ----------------
// out = Σ_s (scale_s ⊙ A) @ W_s.  16 chunks of K=32; per chunk: 1 A tile + 3 B tiles.
#define BM 128
#define SW 20                          // 32-bit words per row (16 used + 4 pad)
#define NCH3 16                        // 512 / 32
#define TILE_B (BM * SW * 4)           // 10240 bytes per tile
#define STAGE_B (4 * TILE_B)           // A + 3 B
#define GM_DYN (2 * STAGE_B)           // 81920

__global__ __launch_bounds__(256, 2) void k_gemm(const __half* __restrict__ WtH,
                                                 const float* __restrict__ bl) {
    extern __shared__ unsigned dynS[];
    __shared__ float sBias[DD];
    __shared__ float sSum[DD], sSq[DD];
    __shared__ unsigned sAmp2[BM], sAtt2[BM];   // half2 broadcast per row

    int bm = blockIdx.x * BM;
    int tid = threadIdx.x;
    int lane = tid & 31;
    int warp = tid >> 5;
    int g = lane >> 2;
    int t = lane & 3;
    int m_base = (warp >> 2) * 64;
    int n_base = (warp & 3) * 32;

    if (tid < DD) {
        sBias[tid] = bl[tid];
        sSum[tid] = 0.f;
        sSq[tid] = 0.f;
        int r = bm + tid;
        float af = (r < NN) ? g_amp[r] : 1.f;
        float tf = (r < NN) ? g_att[r] : 1.f;
        sAmp2[tid] = packh2(af, af);
        sAtt2[tid] = packh2(tf, tf);
    }
    __syncthreads();

    float acc[4][4][4];
#pragma unroll
    for (int i = 0; i < 4; i++)
#pragma unroll
        for (int j = 0; j < 4; j++)
#pragma unroll
            for (int c = 0; c < 4; c++) acc[i][j][c] = 0.f;

    const int cpRow = tid >> 2;
    const int cpSeg = tid & 3;
    const int row2 = cpRow + 64;

    const unsigned base = (unsigned)__cvta_generic_to_shared(&dynS[0]);

    auto cpAB = [&](int chunk, int buf) {
        unsigned st = base + buf * STAGE_B;
#pragma unroll
        for (int u = 0; u < 2; u++) {
            int row = u ? row2 : cpRow;
            unsigned dst = (unsigned)(row * SW + cpSeg * 4) * 4u;
            const unsigned* pa = g_aggsH + (size_t)(bm + row) * 256 + chunk * 16 + cpSeg * 4;
            cp_async16p(st + dst, pa, (bm + row) < NN ? 16 : 0);
#pragma unroll
            for (int s = 0; s < 3; s++)
                cp_async16(st + (1 + s) * TILE_B + dst,
                           WtH + (size_t)row * 1536 + s * 512 + chunk * 32 + cpSeg * 8);
        }
    };

    // ldmatrix lane offsets (bytes within tile)
    const int l8 = lane & 7;
    const unsigned aLane = (unsigned)((l8 + ((lane >> 3) & 1) * 8) * SW * 4 + ((lane >> 4) & 1) * 16);
    const unsigned bLane = (unsigned)((l8 + ((lane >> 4) & 1) * 8) * SW * 4 + ((lane >> 3) & 1) * 16);

    auto mmaChunk = [&](int buf) {
        unsigned st = base + buf * STAGE_B;
        unsigned aB = st + (unsigned)(m_base * SW * 4) + aLane;
        unsigned bB = st + TILE_B + (unsigned)(n_base * SW * 4) + bLane;
#pragma unroll
        for (int ks = 0; ks < 2; ks++) {
            unsigned bf[3][4][2];
#pragma unroll
            for (int s = 0; s < 3; s++) {
                unsigned bb = bB + s * TILE_B;
                ldsm_x4(bf[s][0][0], bf[s][0][1], bf[s][1][0], bf[s][1][1], bb + ks * 32);
                ldsm_x4(bf[s][2][0], bf[s][2][1], bf[s][3][0], bf[s][3][1], bb + 16 * SW * 4 + ks * 32);
            }
#pragma unroll
            for (int i = 0; i < 4; i++) {
                unsigned a0, a1, a2, a3;
                ldsm_x4(a0, a1, a2, a3, aB + (unsigned)(i * 16 * SW * 4) + ks * 32);
                // slab 0: unscaled
#pragma unroll
                for (int j = 0; j < 4; j++)
                    MMA16816(acc[i][j], a0, a1, a2, a3, bf[0][j][0], bf[0][j][1]);
                int rl = m_base + i * 16 + g;
                // slab 1: amp-scaled
                {
                    unsigned sl = sAmp2[rl], sh = sAmp2[rl + 8];
                    unsigned u0 = hmul2u(a0, sl), u1 = hmul2u(a1, sh);
                    unsigned u2 = hmul2u(a2, sl), u3 = hmul2u(a3, sh);
#pragma unroll
                    for (int j = 0; j < 4; j++)
                        MMA16816(acc[i][j], u0, u1, u2, u3, bf[1][j][0], bf[1][j][1]);
                }
                // slab 2: att-scaled
                {
                    unsigned sl = sAtt2[rl], sh = sAtt2[rl + 8];
                    unsigned u0 = hmul2u(a0, sl), u1 = hmul2u(a1, sh);
                    unsigned u2 = hmul2u(a2, sl), u3 = hmul2u(a3, sh);
#pragma unroll
                    for (int j = 0; j < 4; j++)
                        MMA16816(acc[i][j], u0, u1, u2, u3, bf[2][j][0], bf[2][j][1]);
                }
            }
        }
    };

    cpAB(0, 0);
    cp_commit();

    for (int c = 0; c < NCH3; c++) {
        cp_wait0();
        __syncthreads();
        if (c + 1 < NCH3) {
            cpAB(c + 1, (c + 1) & 1);
            cp_commit();
        }
        mmaChunk(c & 1);
    }

    // epilogue: bias + store
#pragma unroll
    for (int i = 0; i < 4; i++) {
        int r0 = bm + m_base + i * 16 + g;
        int r1 = r0 + 8;
#pragma unroll
        for (int j = 0; j < 4; j++) {
            int col = n_base + j * 8 + t * 2;
            float bx = sBias[col], by = sBias[col + 1];
            acc[i][j][0] += bx; acc[i][j][1] += by;
            acc[i][j][2] += bx; acc[i][j][3] += by;
            if (r0 < NN)
                *(float2*)&g_out[(size_t)r0 * DD + col] = make_float2(acc[i][j][0], acc[i][j][1]);
            if (r1 < NN)
                *(float2*)&g_out[(size_t)r1 * DD + col] = make_float2(acc[i][j][2], acc[i][j][3]);
        }
    }

    // fused BN stats: per-column sum/sumsq over valid rows
#pragma unroll
    for (int j = 0; j < 4; j++)
#pragma unroll
        for (int c2 = 0; c2 < 2; c2++) {
            int col = n_base + j * 8 + t * 2 + c2;
            float s = 0.f, q = 0.f;
#pragma unroll
            for (int i = 0; i < 4; i++) {
                int r0 = bm + m_base + i * 16 + g;
                float v0 = acc[i][j][c2];
                float v1 = acc[i][j][2 + c2];
                if (r0 < NN) { s += v0; q += v0 * v0; }
                if (r0 + 8 < NN) { s += v1; q += v1 * v1; }
            }
#pragma unroll
            for (int m = 4; m <= 16; m <<= 1) {
                s += __shfl_xor_sync(0xffffffffu, s, m);
                q += __shfl_xor_sync(0xffffffffu, q, m);
            }
            if (g == 0) {
                atomicAdd(&sSum[col], s);
                atomicAdd(&sSq[col], q);
            }
        }
    __syncthreads();
    if (tid < DD) {
        atomicAdd(&g_bnsum[tid], sSum[tid]);
        atomicAdd(&g_bnsq[tid], sSq[tid]);
    }
}

// BN apply with inline param computation + residual + fp16 mirror
__global__ void k_bnapply(const float* __restrict__ gamma, const float* __restrict__ beta) {
    int t = blockIdx.x * blockDim.x + threadIdx.x;
    if (t >= NN * 32) return;
    int c = (t & 31) * 4;
    float mu[4], rsg[4], bt[4];
#pragma unroll
    for (int u = 0; u < 4; u++) {
        float m = g_bnsum[c + u] / (float)NN;
        float var = g_bnsq[c + u] / (float)NN - m * m;
        mu[u] = m;
        rsg[u] = rsqrtf(var + EPSF) * gamma[c + u];
        bt[u] = beta[c + u];
    }
    float4 o = ((const float4*)g_out)[t];
    float4 h = ((float4*)g_h)[t];
    o.x = fmaxf((o.x - mu[0]) * rsg[0] + bt[0], 0.f) + h.x;
    o.y = fmaxf((o.y - mu[1]) * rsg[1] + bt[1], 0.f) + h.y;
    o.z = fmaxf((o.z - mu[2]) * rsg[2] + bt[2], 0.f) + h.z;
    o.w = fmaxf((o.w - mu[3]) * rsg[3] + bt[3], 0.f) + h.w;
    ((float4*)g_h)[t] = o;
    ((uint2*)g_hH)[t] = make_uint2(packh2(o.x, o.y), packh2(o.z, o.w));
}

// ---------------- fused pooling + MLP: one block per graph ----------------
__global__ void k_poolmlp(const float* __restrict__ W1, const float* __restrict__ b1,
                          const float* __restrict__ W2, const float* __restrict__ b2,
                          const float* __restrict__ W3, const float* __restrict__ b3,
                          float* __restrict__ out) {
    __shared__ float sg[DD], sz1[64], sz2[32];
    int gid = blockIdx.x;
    int tid = threadIdx.x;      // 128 threads, one per feature
    int beg = g_goff[gid], end = g_goff[gid + 1];
    float s = 0.f;
    for (int r = beg; r < end; r++) s += g_h[(size_t)r * DD + tid];
    sg[tid] = s / (float)max(end - beg, 1);
    __syncthreads();
    if (tid < 64) {
        float a = b1[tid];
        for (int k = 0; k < DD; k++) a += sg[k] * W1[k * 64 + tid];
        sz1[tid] = fmaxf(a, 0.f);
    }
    __syncthreads();
    if (tid < 32) {
        float a = b2[tid];
        for (int k = 0; k < 64; k++) a += sz1[k] * W2[k * 32 + tid];
        sz2[tid] = fmaxf(a, 0.f);
    }
    __syncthreads();
    if (tid < NT) {
        float a = b3[tid];
        for (int k = 0; k < 32; k++) a += sz2[k] * W3[k * NT + tid];
        out[gid * NT + tid] = a;
    }
}

// ---------------- launch ----------------
extern "C" void kernel_launch(void* const* d_in, const int* in_sizes, int n_in,
                              void* d_out, int out_size) {
    const float* x      = (const float*)d_in[0];
    const int*   ei     = (const int*)d_in[1];
    const int*   batch  = (const int*)d_in[2];
    const float* emb_W  = (const float*)d_in[3];
    const float* emb_b  = (const float*)d_in[4];
    const float* conv_W = (const float*)d_in[5];
    const float* conv_b = (const float*)d_in[6];
    const float* bng    = (const float*)d_in[7];
    const float* bnb    = (const float*)d_in[8];
    const float* W1     = (const float*)d_in[9];
    const float* b1     = (const float*)d_in[10];
    const float* W2     = (const float*)d_in[11];
    const float* b2     = (const float*)d_in[12];
    const float* W3     = (const float*)d_in[13];
    const float* b3     = (const float*)d_in[14];
    float* out = (float*)d_out;

    cudaFuncSetAttribute(k_gemm, cudaFuncAttributeMaxDynamicSharedMemorySize, GM_DYN);

    k_zero<<<(NN + 255) / 256, 256>>>();
    k_hist<<<(NE + 255) / 256, 256>>>(ei, batch);
    k_scan<<<1, 1024>>>();
    k_delta<<<(NN + 255) / 256, 256>>>();
    k_scalars<<<(NN + 255) / 256, 256>>>();
    k_scatter<<<(NE + 255) / 256, 256>>>(ei);
    k_emb<<<(NN * 32 + 255) / 256, 256>>>(x, emb_W, emb_b);
    k_wprep<<<(NL * 1536 * DD + 255) / 256, 256>>>(conv_W);

    __half* g_WtH_ptr;
    cudaGetSymbolAddress((void**)&g_WtH_ptr, g_WtH);

    for (int l = 0; l < NL; l++) {
        k_agg<<<(NN * 32 + 255) / 256, 256>>>();
        k_gemm<<<(NN + BM - 1) / BM, 256, GM_DYN>>>(g_WtH_ptr + (size_t)l * DD * 1536,
                                                    conv_b + (size_t)l * DD);
        k_bnapply<<<(NN * 32 + 255) / 256, 256>>>(bng + (size_t)l * DD, bnb + (size_t)l * DD);
    }

    k_poolmlp<<<NG, DD>>>(W1, b1, W2, b2, W3, b3, out);
}